// round 1
// baseline (speedup 1.0000x reference)
#include <cuda_runtime.h>
#include <cstdint>

// ---------------------------------------------------------------------------
// PSA fused kernel: per-window attention block, fp32 with packed f32x2 FMA.
//   x[4096,64,256] -> qkv proj -> 8-head attn(+bias+mask, softmax) -> out proj
// One CTA per window. All intermediates in shared memory.
// ---------------------------------------------------------------------------

#define NTOK   64
#define DIMC   256
#define KVD    128
#define NHEAD  8
#define HDIM   16
#define PSA_SCALE 0.17677669529663687f   // (256/8)^-0.5

typedef unsigned long long u64;

// Pre-gathered relative position bias: [H][64][64]
__device__ float g_bias[NHEAD * NTOK * NTOK];

__global__ void psa_bias_kernel(const float* __restrict__ bt,
                                const int* __restrict__ ri) {
    int ij = blockIdx.x * 64 + threadIdx.x;   // 4096 (i,j) pairs
    int idx = ri[ij];
#pragma unroll
    for (int h = 0; h < NHEAD; h++)
        g_bias[h * (NTOK * NTOK) + ij] = bt[idx * NHEAD + h];
}

__device__ __forceinline__ u64 pk2(float lo, float hi) {
    u64 r; asm("mov.b64 %0, {%1,%2};" : "=l"(r) : "f"(lo), "f"(hi)); return r;
}
__device__ __forceinline__ float2 upk2(u64 v) {
    float2 r; asm("mov.b64 {%0,%1}, %2;" : "=f"(r.x), "=f"(r.y) : "l"(v)); return r;
}
__device__ __forceinline__ void fma2(u64& d, u64 a, u64 b) {
    asm("fma.rn.f32x2 %0, %1, %2, %0;" : "+l"(d) : "l"(a), "l"(b));
}

// Shared memory layout (floats):
//   xs   [64][256]   16384   (overlaid later by ao [64][130])
//   qkv  [64][384]   24576   (q: cols 0..127, k: 128..255, v: 256..383)
//   wt   [32][128]    4096   (transposed weight tile, K-major)
//   msk  [64][64]     4096
// total 49152 floats = 196608 bytes

__global__ void __launch_bounds__(512, 1) psa_main_kernel(
    const float* __restrict__ x,      const float* __restrict__ mask,
    const float* __restrict__ q_w,    const float* __restrict__ q_b,
    const float* __restrict__ kv_w,   const float* __restrict__ kv_b,
    const float* __restrict__ proj_w, const float* __restrict__ proj_b,
    float* __restrict__ out)
{
    extern __shared__ float sm[];
    float* xs  = sm;                       // [64][256]
    float* qkv = sm + 64 * 256;            // [64][384]
    float* wt  = qkv + 64 * 384;           // [32][128]
    float* msk = wt + 32 * 128;            // [64][64]
    float* ao  = sm;                       // overlay: [64][130] (pitch 130)

    const int t = threadIdx.x;
    const int w = blockIdx.x;

    // ---- stage x tile and mask tile (coalesced float4 copies) ----
    {
        const float4* xg4 = (const float4*)(x + (size_t)w * (NTOK * DIMC));
        float4* xs4 = (float4*)xs;
#pragma unroll
        for (int r = 0; r < 8; r++) xs4[t + 512 * r] = xg4[t + 512 * r];
        const float4* mg4 = (const float4*)(mask + (size_t)(w & 63) * (NTOK * NTOK));
        float4* ms4 = (float4*)msk;
#pragma unroll
        for (int r = 0; r < 2; r++) ms4[t + 512 * r] = mg4[t + 512 * r];
    }

    // thread tiling for GEMM phases: 4 rows x 4 cols per thread
    const int tj = t & 31, ti = t >> 5;
    const int i0 = ti * 4, j0 = tj * 4;

    // =====================================================================
    // Phase B: qkv[64][384] = xs[64][256] @ W^T + b   (3 chunks of 128 cols)
    // =====================================================================
#pragma unroll 1
    for (int ch = 0; ch < 3; ch++) {
        const float* W    = (ch == 0) ? q_w : (kv_w + (ch - 1) * (128 * 256));
        const float* bias = (ch == 0) ? q_b : (kv_b + (ch - 1) * 128);
        u64 acc[4][2];
        {
            u64 p01 = pk2(bias[j0],     bias[j0 + 1]);
            u64 p23 = pk2(bias[j0 + 2], bias[j0 + 3]);
#pragma unroll
            for (int r = 0; r < 4; r++) { acc[r][0] = p01; acc[r][1] = p23; }
        }
#pragma unroll 1
        for (int ct = 0; ct < 8; ct++) {       // K slabs of 32
            __syncthreads();
            {   // stage wt[c][j] = W[j][ct*32+c]  (transposed)
                int j = t & 127, g = t >> 7;
#pragma unroll
                for (int r = 0; r < 2; r++) {
                    int c4 = g * 2 + r;
                    float4 v = *(const float4*)&W[j * 256 + ct * 32 + c4 * 4];
                    wt[(c4 * 4 + 0) * 128 + j] = v.x;
                    wt[(c4 * 4 + 1) * 128 + j] = v.y;
                    wt[(c4 * 4 + 2) * 128 + j] = v.z;
                    wt[(c4 * 4 + 3) * 128 + j] = v.w;
                }
            }
            __syncthreads();
#pragma unroll
            for (int cc = 0; cc < 32; cc++) {
                int c = ct * 32 + cc;
                float x0 = xs[(i0 + 0) * 256 + c];
                float x1 = xs[(i0 + 1) * 256 + c];
                float x2 = xs[(i0 + 2) * 256 + c];
                float x3 = xs[(i0 + 3) * 256 + c];
                ulonglong2 wv = *(const ulonglong2*)&wt[cc * 128 + j0];
                u64 xp;
                xp = pk2(x0, x0); fma2(acc[0][0], xp, wv.x); fma2(acc[0][1], xp, wv.y);
                xp = pk2(x1, x1); fma2(acc[1][0], xp, wv.x); fma2(acc[1][1], xp, wv.y);
                xp = pk2(x2, x2); fma2(acc[2][0], xp, wv.x); fma2(acc[2][1], xp, wv.y);
                xp = pk2(x3, x3); fma2(acc[3][0], xp, wv.x); fma2(acc[3][1], xp, wv.y);
            }
        }
        int base = ch * 128;
#pragma unroll
        for (int r = 0; r < 4; r++) {
            *(u64*)&qkv[(i0 + r) * 384 + base + j0]     = acc[r][0];
            *(u64*)&qkv[(i0 + r) * 384 + base + j0 + 2] = acc[r][1];
        }
    }
    __syncthreads();   // qkv complete; xs is dead from here on

    // =====================================================================
    // Phase C: attention. 2 warps per head; each lane owns one full row.
    // =====================================================================
    const int lane = t & 31;
    const int h    = t >> 6;                       // head 0..7
    const int irow = ((t >> 5) & 1) * 32 + lane;   // row 0..63

    u64 q2[8];
    {
        const float* qrow = &qkv[irow * 384 + h * HDIM];
#pragma unroll
        for (int e = 0; e < 8; e++) q2[e] = *(const u64*)&qrow[2 * e];
    }

    float attn[64];
#pragma unroll
    for (int jj = 0; jj < 64; jj++) {              // Q . K^T (d-pairs packed)
        const float* krow = &qkv[jj * 384 + 128 + h * HDIM];
        u64 a2 = pk2(0.f, 0.f);
#pragma unroll
        for (int e = 0; e < 8; e++) {
            u64 k2 = *(const u64*)&krow[2 * e];
            fma2(a2, q2[e], k2);
        }
        float2 f = upk2(a2);
        attn[jj] = f.x + f.y;
    }

    const float* bb   = &g_bias[(h * 64 + irow) * 64];
    const float* mrow = &msk[irow * 64];
    float mx = -3.0e38f;
#pragma unroll
    for (int jj = 0; jj < 64; jj++) {
        float v = attn[jj] * PSA_SCALE + __ldg(bb + jj) + mrow[jj];
        attn[jj] = v;
        mx = fmaxf(mx, v);
    }
    float s = 0.f;
#pragma unroll
    for (int jj = 0; jj < 64; jj++) {
        float e = __expf(attn[jj] - mx);
        attn[jj] = e;
        s += e;
    }
    float inv = 1.0f / s;

    u64 o2[8];
#pragma unroll
    for (int e = 0; e < 8; e++) o2[e] = pk2(0.f, 0.f);
#pragma unroll
    for (int jj = 0; jj < 64; jj++) {              // P @ V (d-pairs packed)
        float p = attn[jj] * inv;
        u64 p2 = pk2(p, p);
        const float* vrow = &qkv[jj * 384 + 256 + h * HDIM];
#pragma unroll
        for (int e = 0; e < 8; e++) {
            u64 v2 = *(const u64*)&vrow[2 * e];
            fma2(o2[e], p2, v2);
        }
    }
    // attention output -> ao[irow][h*16 + d] (overlays dead xs region;
    // ao (33280 B) < xs (65536 B), so still-live qkv reads are untouched)
#pragma unroll
    for (int e = 0; e < 8; e++)
        *(u64*)&ao[irow * 130 + h * HDIM + 2 * e] = o2[e];
    __syncthreads();

    // =====================================================================
    // Phase D: out[64][256] = ao[64][128] @ proj_w^T + proj_b
    // =====================================================================
#pragma unroll 1
    for (int ch = 0; ch < 2; ch++) {
        u64 acc[4][2];
        {
            const float* pb = proj_b + ch * 128;
            u64 p01 = pk2(pb[j0],     pb[j0 + 1]);
            u64 p23 = pk2(pb[j0 + 2], pb[j0 + 3]);
#pragma unroll
            for (int r = 0; r < 4; r++) { acc[r][0] = p01; acc[r][1] = p23; }
        }
#pragma unroll 1
        for (int ct = 0; ct < 4; ct++) {           // K slabs of 32 (K=128)
            __syncthreads();
            {
                int j = t & 127, g = t >> 7;
#pragma unroll
                for (int r = 0; r < 2; r++) {
                    int c4 = g + 4 * r;
                    float4 v = *(const float4*)&proj_w[(ch * 128 + j) * 128 + ct * 32 + c4 * 4];
                    wt[(c4 * 4 + 0) * 128 + j] = v.x;
                    wt[(c4 * 4 + 1) * 128 + j] = v.y;
                    wt[(c4 * 4 + 2) * 128 + j] = v.z;
                    wt[(c4 * 4 + 3) * 128 + j] = v.w;
                }
            }
            __syncthreads();
#pragma unroll
            for (int cc = 0; cc < 32; cc++) {
                int d = ct * 32 + cc;
                float a0 = ao[(i0 + 0) * 130 + d];
                float a1 = ao[(i0 + 1) * 130 + d];
                float a2 = ao[(i0 + 2) * 130 + d];
                float a3 = ao[(i0 + 3) * 130 + d];
                ulonglong2 wv = *(const ulonglong2*)&wt[cc * 128 + j0];
                u64 xp;
                xp = pk2(a0, a0); fma2(acc[0][0], xp, wv.x); fma2(acc[0][1], xp, wv.y);
                xp = pk2(a1, a1); fma2(acc[1][0], xp, wv.x); fma2(acc[1][1], xp, wv.y);
                xp = pk2(a2, a2); fma2(acc[2][0], xp, wv.x); fma2(acc[2][1], xp, wv.y);
                xp = pk2(a3, a3); fma2(acc[3][0], xp, wv.x); fma2(acc[3][1], xp, wv.y);
            }
        }
        float* og = out + (size_t)w * (NTOK * DIMC) + ch * 128;
#pragma unroll
        for (int r = 0; r < 4; r++) {
            float2 lo = upk2(acc[r][0]);
            float2 hi = upk2(acc[r][1]);
            float4 v = make_float4(lo.x, lo.y, hi.x, hi.y);
            *(float4*)&og[(i0 + r) * 256 + j0] = v;
        }
    }
}

extern "C" void kernel_launch(void* const* d_in, const int* in_sizes, int n_in,
                              void* d_out, int out_size) {
    const float* x      = (const float*)d_in[0];
    const float* mask   = (const float*)d_in[1];
    const float* q_w    = (const float*)d_in[2];
    const float* q_b    = (const float*)d_in[3];
    const float* kv_w   = (const float*)d_in[4];
    const float* kv_b   = (const float*)d_in[5];
    const float* proj_w = (const float*)d_in[6];
    const float* proj_b = (const float*)d_in[7];
    const float* bt     = (const float*)d_in[8];
    const int*   ri     = (const int*)d_in[9];
    float* out = (float*)d_out;

    cudaFuncSetAttribute(psa_main_kernel,
                         cudaFuncAttributeMaxDynamicSharedMemorySize, 196608);

    psa_bias_kernel<<<64, 64>>>(bt, ri);
    psa_main_kernel<<<4096, 512, 196608>>>(x, mask, q_w, q_b, kv_w, kv_b,
                                           proj_w, proj_b, out);
}

// round 3
// speedup vs baseline: 2.4244x; 2.4244x over previous
#include <cuda_runtime.h>
#include <cuda_bf16.h>
#include <cstdint>

typedef unsigned long long u64;
typedef unsigned int u32;

#define NTOK 64
#define NHEAD 8
#define PSA_SCALE 0.17677669529663687f
#define NWIN 4096

// ---------------------------------------------------------------------------
// Device scratch (static module allocations)
// ---------------------------------------------------------------------------
__device__ float4 g_qkv4[(size_t)NWIN * NTOK * 384 / 4];   // 402 MB qkv fp32
__device__ float4 g_ao4[(size_t)NWIN * NTOK * 128 / 4];    // 134 MB attn out
__device__ __nv_bfloat16 g_w1h[384 * 256];                 // split bf16 weights
__device__ __nv_bfloat16 g_w1l[384 * 256];
__device__ __nv_bfloat16 g_w2h[256 * 128];
__device__ __nv_bfloat16 g_w2l[256 * 128];
__device__ float g_b1[384];
__device__ float g_cmb[64 * NHEAD * NTOK * NTOK];          // bias+mask combined

// ---------------------------------------------------------------------------
// Helpers
// ---------------------------------------------------------------------------
__device__ __forceinline__ u32 smem_u32(const void* p) {
    u32 a;
    asm("{ .reg .u64 t; cvta.to.shared.u64 t, %1; cvt.u32.u64 %0, t; }"
        : "=r"(a) : "l"(p));
    return a;
}
__device__ __forceinline__ void ldsm4(u32* r, u32 addr) {
    asm volatile("ldmatrix.sync.aligned.m8n8.x4.shared.b16 {%0,%1,%2,%3}, [%4];"
                 : "=r"(r[0]), "=r"(r[1]), "=r"(r[2]), "=r"(r[3]) : "r"(addr));
}
__device__ __forceinline__ void mma_bf16(float* c, const u32* a, const u32* b) {
    asm volatile(
        "mma.sync.aligned.m16n8k16.row.col.f32.bf16.bf16.f32 "
        "{%0,%1,%2,%3}, {%4,%5,%6,%7}, {%8,%9}, {%0,%1,%2,%3};"
        : "+f"(c[0]), "+f"(c[1]), "+f"(c[2]), "+f"(c[3])
        : "r"(a[0]), "r"(a[1]), "r"(a[2]), "r"(a[3]), "r"(b[0]), "r"(b[1]));
}
__device__ __forceinline__ u32 b2u(__nv_bfloat162 v) { return *reinterpret_cast<u32*>(&v); }

__device__ __forceinline__ u64 pk2(float lo, float hi) {
    u64 r; asm("mov.b64 %0, {%1,%2};" : "=l"(r) : "f"(lo), "f"(hi)); return r;
}
__device__ __forceinline__ float2 upk2(u64 v) {
    float2 r; asm("mov.b64 {%0,%1}, %2;" : "=f"(r.x), "=f"(r.y) : "l"(v)); return r;
}
__device__ __forceinline__ void fma2(u64& d, u64 a, u64 b) {
    asm("fma.rn.f32x2 %0, %1, %2, %0;" : "+l"(d) : "l"(a), "l"(b));
}

// ---------------------------------------------------------------------------
// Prologue kernels
// ---------------------------------------------------------------------------
__global__ void psa_prep_w1(const float* __restrict__ qw,
                            const float* __restrict__ kvw) {
    int n = blockIdx.x, k = threadIdx.x;            // 384 x 256
    float v = (n < 128) ? qw[n * 256 + k] : kvw[(n - 128) * 256 + k];
    __nv_bfloat16 h = __float2bfloat16_rn(v);
    __nv_bfloat16 l = __float2bfloat16_rn(v - __bfloat162float(h));
    g_w1h[n * 256 + k] = h;
    g_w1l[n * 256 + k] = l;
}
__global__ void psa_prep_w2(const float* __restrict__ pw) {
    int n = blockIdx.x, k = threadIdx.x;            // 256 x 128
    float v = pw[n * 128 + k];
    __nv_bfloat16 h = __float2bfloat16_rn(v);
    __nv_bfloat16 l = __float2bfloat16_rn(v - __bfloat162float(h));
    g_w2h[n * 128 + k] = h;
    g_w2l[n * 128 + k] = l;
}
__global__ void psa_prep_b1(const float* __restrict__ qb,
                            const float* __restrict__ kvb) {
    int i = threadIdx.x;
    g_b1[i] = (i < 128) ? qb[i] : kvb[i - 128];
}
// cmb[nw][h][i][j] = bias_table[ri[i,j]][h] + mask[nw][i][j]
__global__ void psa_prep_cmb(const float* __restrict__ bt,
                             const int* __restrict__ ri,
                             const float* __restrict__ mask) {
    int idx = blockIdx.x * 512 + threadIdx.x;       // 2M elements
    int j = idx & 63, i = (idx >> 6) & 63, h = (idx >> 12) & 7, nw = idx >> 15;
    g_cmb[idx] = bt[ri[i * 64 + j] * NHEAD + h] + mask[nw * 4096 + i * 64 + j];
}

// ---------------------------------------------------------------------------
// HMMA split-bf16 GEMM:  out[M,N] = A[M,K] @ W[N,K]^T + bias
// CTA: M=128, 256 threads (warp grid 4M x 2N, warp tile 32x32), N chunks of 64.
// ---------------------------------------------------------------------------
template <int K, int NCHUNKS>
__global__ void __launch_bounds__(256, 1) psa_hmma_gemm(
    const float* __restrict__ A,
    const __nv_bfloat16* __restrict__ Whg, const __nv_bfloat16* __restrict__ Wlg,
    const float* __restrict__ bias,
    float* __restrict__ out)
{
    constexpr int N  = NCHUNKS * 64;
    constexpr int PK = K + 8;                       // padded bf16 pitch
    constexpr int KG = K / 8;                       // uint4 per row (gmem)
    constexpr int OFF_AL = 128 * PK * 2;            // bytes
    constexpr int OFF_W  = 2 * 128 * PK * 2;
    constexpr int OFF_WL = OFF_W + 64 * PK * 2;

    extern __shared__ char smem[];
    const u32 sb = smem_u32(smem);
    float* stag = (float*)(smem + OFF_W);           // overlaps W region (time-shared)

    const int t = threadIdx.x, lane = t & 31, wid = t >> 5;
    const int m0 = (wid & 3) * 32, n0 = (wid >> 2) * 32;

    // ---- convert A tile (128 x K fp32) -> Ah/Al bf16, padded rows ----
    {
        const float* Ag = A + (size_t)blockIdx.x * 128 * K;
#pragma unroll 4
        for (int u = t; u < 128 * KG; u += 256) {
            int r = u / KG, k0 = (u % KG) * 8;
            float4 a = *(const float4*)(Ag + r * K + k0);
            float4 b = *(const float4*)(Ag + r * K + k0 + 4);
            __nv_bfloat162 h0 = __float22bfloat162_rn(make_float2(a.x, a.y));
            __nv_bfloat162 h1 = __float22bfloat162_rn(make_float2(a.z, a.w));
            __nv_bfloat162 h2 = __float22bfloat162_rn(make_float2(b.x, b.y));
            __nv_bfloat162 h3 = __float22bfloat162_rn(make_float2(b.z, b.w));
            float2 f0 = __bfloat1622float2(h0), f1 = __bfloat1622float2(h1);
            float2 f2 = __bfloat1622float2(h2), f3 = __bfloat1622float2(h3);
            __nv_bfloat162 l0 = __float22bfloat162_rn(make_float2(a.x - f0.x, a.y - f0.y));
            __nv_bfloat162 l1 = __float22bfloat162_rn(make_float2(a.z - f1.x, a.w - f1.y));
            __nv_bfloat162 l2 = __float22bfloat162_rn(make_float2(b.x - f2.x, b.y - f2.y));
            __nv_bfloat162 l3 = __float22bfloat162_rn(make_float2(b.z - f3.x, b.w - f3.y));
            int off = r * (PK * 2) + k0 * 2;
            *(uint4*)(smem + off)          = make_uint4(b2u(h0), b2u(h1), b2u(h2), b2u(h3));
            *(uint4*)(smem + OFF_AL + off) = make_uint4(b2u(l0), b2u(l1), b2u(l2), b2u(l3));
        }
    }

    // per-lane ldmatrix base offsets (bytes, chunk-invariant)
    u32 a_off[2], w_off[2];
#pragma unroll
    for (int mi = 0; mi < 2; mi++)
        a_off[mi] = (u32)((m0 + mi * 16 + (lane & 15)) * (PK * 2) + (lane >> 4) * 16);
    {
        int brow = ((lane >> 4) & 1) * 8 + (lane & 7);
        int bko  = ((lane >> 3) & 1) * 16;
#pragma unroll
        for (int nj = 0; nj < 2; nj++)
            w_off[nj] = (u32)((n0 + nj * 16 + brow) * (PK * 2) + bko);
    }

#pragma unroll 1
    for (int ch = 0; ch < NCHUNKS; ch++) {
        __syncthreads();   // staging copy (prev chunk) / A-conv done
        // ---- stage W chunk (64 x K bf16, hi+lo) ----
        {
            const uint4* gh = (const uint4*)(Whg + (size_t)ch * 64 * K);
            const uint4* gl = (const uint4*)(Wlg + (size_t)ch * 64 * K);
#pragma unroll 4
            for (int i = t; i < 64 * KG; i += 256) {
                int row = i / KG, j = i % KG;
                *(uint4*)(smem + OFF_W  + row * (PK * 2) + j * 16) = gh[i];
                *(uint4*)(smem + OFF_WL + row * (PK * 2) + j * 16) = gl[i];
            }
        }
        __syncthreads();

        // ---- accumulators init with bias ----
        float c[2][4][4];
#pragma unroll
        for (int ni = 0; ni < 4; ni++) {
            int col = ch * 64 + n0 + ni * 8 + (lane & 3) * 2;
            float b0 = __ldg(bias + col), b1 = __ldg(bias + col + 1);
#pragma unroll
            for (int mi = 0; mi < 2; mi++) {
                c[mi][ni][0] = b0; c[mi][ni][1] = b1;
                c[mi][ni][2] = b0; c[mi][ni][3] = b1;
            }
        }

        // ---- K loop: 3-term split-bf16 HMMA ----
#pragma unroll 2
        for (int k0 = 0; k0 < K; k0 += 16) {
            u32 ah[2][4], al[2][4], wh[2][4], wl[2][4];
#pragma unroll
            for (int mi = 0; mi < 2; mi++) {
                ldsm4(ah[mi], sb + a_off[mi] + k0 * 2);
                ldsm4(al[mi], sb + OFF_AL + a_off[mi] + k0 * 2);
            }
#pragma unroll
            for (int nj = 0; nj < 2; nj++) {
                ldsm4(wh[nj], sb + OFF_W  + w_off[nj] + k0 * 2);
                ldsm4(wl[nj], sb + OFF_WL + w_off[nj] + k0 * 2);
            }
#pragma unroll
            for (int mi = 0; mi < 2; mi++)
#pragma unroll
                for (int nt = 0; nt < 4; nt++) {
                    mma_bf16(c[mi][nt], ah[mi], &wh[nt >> 1][(nt & 1) * 2]);
                    mma_bf16(c[mi][nt], ah[mi], &wl[nt >> 1][(nt & 1) * 2]);
                    mma_bf16(c[mi][nt], al[mi], &wh[nt >> 1][(nt & 1) * 2]);
                }
        }
        __syncthreads();   // all warps done reading W before staging overwrite

        // ---- frags -> staging (pitch 72) ----
        {
            int rq = lane >> 2, cq = (lane & 3) * 2;
#pragma unroll
            for (int mi = 0; mi < 2; mi++)
#pragma unroll
                for (int ni = 0; ni < 4; ni++) {
                    int rr = m0 + mi * 16 + rq, cc = n0 + ni * 8 + cq;
                    *(float2*)&stag[rr * 72 + cc]       = make_float2(c[mi][ni][0], c[mi][ni][1]);
                    *(float2*)&stag[(rr + 8) * 72 + cc] = make_float2(c[mi][ni][2], c[mi][ni][3]);
                }
        }
        __syncthreads();

        // ---- coalesced copy staging -> gmem ----
#pragma unroll
        for (int i = 0; i < 8; i++) {
            int idx = t + 256 * i;
            int r = idx >> 4, c4 = (idx & 15) * 4;
            float4 v = *(float4*)&stag[r * 72 + c4];
            *(float4*)(out + ((size_t)blockIdx.x * 128 + r) * N + ch * 64 + c4) = v;
        }
    }
}

// ---------------------------------------------------------------------------
// Attention: one window per CTA, 512 threads, lane = (head, row).
// k/v in per-head smem (broadcast reads); bias+mask from combined L2 table.
// ---------------------------------------------------------------------------
__global__ void __launch_bounds__(512, 1) psa_attn_kernel(
    const float4* __restrict__ qkvg, const float* __restrict__ cmbg,
    float* __restrict__ aog)
{
    extern __shared__ float sm[];
    float* qs = sm;            // [64][132]
    float* ks = sm + 8448;     // [8][64][16]
    float* vs = ks + 8192;     // [8][64][16]
    const int t = threadIdx.x, w = blockIdx.x;

    // ---- stage qkv tile ----
    {
        const float4* qg = qkvg + (size_t)w * (NTOK * 384 / 4);
#pragma unroll
        for (int i = 0; i < 12; i++) {
            int idx = t + 512 * i;                   // 64*96 float4
            int row = idx / 96, c = (idx % 96) * 4;
            float4 v = qg[idx];
            if (c < 128) {
                *(float4*)&qs[row * 132 + c] = v;
            } else if (c < 256) {
                int cc = c - 128;
                *(float4*)&ks[(cc >> 4) * 1024 + row * 16 + (cc & 15)] = v;
            } else {
                int cc = c - 256;
                *(float4*)&vs[(cc >> 4) * 1024 + row * 16 + (cc & 15)] = v;
            }
        }
    }
    __syncthreads();

    const int lane = t & 31;
    const int h    = t >> 6;
    const int irow = ((t >> 5) & 1) * 32 + lane;

    u64 q2[8];
    {
        const float* qrow = &qs[irow * 132 + h * 16];
#pragma unroll
        for (int e = 0; e < 8; e++) q2[e] = *(const u64*)&qrow[2 * e];
    }

    float attn[64];
    const float* kh = ks + h * 1024;
#pragma unroll
    for (int jj = 0; jj < 64; jj++) {               // Q . K^T (broadcast k)
        const float* krow = kh + jj * 16;
        u64 a2 = pk2(0.f, 0.f);
#pragma unroll
        for (int e = 0; e < 8; e++) fma2(a2, q2[e], *(const u64*)&krow[2 * e]);
        float2 f = upk2(a2);
        attn[jj] = f.x + f.y;
    }

    const float4* cb = (const float4*)(cmbg + ((((w & 63) * 8 + h) * 64 + irow) << 6));
    float mx = -3.0e38f;
#pragma unroll
    for (int q4 = 0; q4 < 16; q4++) {
        float4 b4 = __ldg(cb + q4);
        float v0 = attn[q4 * 4 + 0] * PSA_SCALE + b4.x;
        float v1 = attn[q4 * 4 + 1] * PSA_SCALE + b4.y;
        float v2 = attn[q4 * 4 + 2] * PSA_SCALE + b4.z;
        float v3 = attn[q4 * 4 + 3] * PSA_SCALE + b4.w;
        attn[q4 * 4 + 0] = v0; attn[q4 * 4 + 1] = v1;
        attn[q4 * 4 + 2] = v2; attn[q4 * 4 + 3] = v3;
        mx = fmaxf(mx, fmaxf(fmaxf(v0, v1), fmaxf(v2, v3)));
    }
    float s = 0.f;
#pragma unroll
    for (int jj = 0; jj < 64; jj++) {
        float e = __expf(attn[jj] - mx);
        attn[jj] = e;
        s += e;
    }
    float inv = 1.0f / s;

    u64 o2[8];
#pragma unroll
    for (int e = 0; e < 8; e++) o2[e] = pk2(0.f, 0.f);
    const float* vh = vs + h * 1024;
#pragma unroll
    for (int jj = 0; jj < 64; jj++) {               // P @ V (broadcast v)
        float p = attn[jj] * inv;
        u64 p2 = pk2(p, p);
        const float* vrow = vh + jj * 16;
#pragma unroll
        for (int e = 0; e < 8; e++) fma2(o2[e], p2, *(const u64*)&vrow[2 * e]);
    }
    float* ob = aog + ((size_t)w * 64 + irow) * 128 + h * 16;
#pragma unroll
    for (int e = 0; e < 4; e++) {
        float2 a = upk2(o2[2 * e]), b = upk2(o2[2 * e + 1]);
        *(float4*)(ob + 4 * e) = make_float4(a.x, a.y, b.x, b.y);
    }
}

// ---------------------------------------------------------------------------
extern "C" void kernel_launch(void* const* d_in, const int* in_sizes, int n_in,
                              void* d_out, int out_size) {
    const float* x      = (const float*)d_in[0];
    const float* mask   = (const float*)d_in[1];
    const float* q_w    = (const float*)d_in[2];
    const float* q_b    = (const float*)d_in[3];
    const float* kv_w   = (const float*)d_in[4];
    const float* kv_b   = (const float*)d_in[5];
    const float* proj_w = (const float*)d_in[6];
    const float* proj_b = (const float*)d_in[7];
    const float* bt     = (const float*)d_in[8];
    const int*   ri     = (const int*)d_in[9];
    float* out = (float*)d_out;

    void *pqkv, *pao, *pw1h, *pw1l, *pw2h, *pw2l, *pb1, *pcmb;
    cudaGetSymbolAddress(&pqkv, g_qkv4);
    cudaGetSymbolAddress(&pao,  g_ao4);
    cudaGetSymbolAddress(&pw1h, g_w1h);
    cudaGetSymbolAddress(&pw1l, g_w1l);
    cudaGetSymbolAddress(&pw2h, g_w2h);
    cudaGetSymbolAddress(&pw2l, g_w2l);
    cudaGetSymbolAddress(&pb1,  g_b1);
    cudaGetSymbolAddress(&pcmb, g_cmb);

    // smem sizes: K=256: 2*128*528 + max(2*64*528, 36864) = 135168+67584
    //             K=128: 2*128*272 + max(2*64*272, 36864) = 69632+36864
    cudaFuncSetAttribute(psa_hmma_gemm<256, 6>,
                         cudaFuncAttributeMaxDynamicSharedMemorySize, 202752);
    cudaFuncSetAttribute(psa_hmma_gemm<128, 4>,
                         cudaFuncAttributeMaxDynamicSharedMemorySize, 106496);
    cudaFuncSetAttribute(psa_attn_kernel,
                         cudaFuncAttributeMaxDynamicSharedMemorySize, 99328);

    psa_prep_w1<<<384, 256>>>(q_w, kv_w);
    psa_prep_w2<<<256, 128>>>(proj_w);
    psa_prep_b1<<<1, 384>>>(q_b, kv_b);
    psa_prep_cmb<<<4096, 512>>>(bt, ri, mask);

    // 1) qkv = x @ [q_w;kv_w]^T + b       (M=262144, K=256, N=384)
    psa_hmma_gemm<256, 6><<<2048, 256, 202752>>>(
        x, (const __nv_bfloat16*)pw1h, (const __nv_bfloat16*)pw1l,
        (const float*)pb1, (float*)pqkv);

    // 2) attention
    psa_attn_kernel<<<4096, 512, 99328>>>(
        (const float4*)pqkv, (const float*)pcmb, (float*)pao);

    // 3) out = ao @ proj_w^T + proj_b     (M=262144, K=128, N=256)
    psa_hmma_gemm<128, 4><<<2048, 256, 106496>>>(
        (const float*)pao, (const __nv_bfloat16*)pw2h, (const __nv_bfloat16*)pw2l,
        proj_b, out);
}

// round 5
// speedup vs baseline: 2.9624x; 1.2219x over previous
#include <cuda_runtime.h>
#include <cuda_fp16.h>
#include <cstdint>

typedef unsigned long long u64;
typedef unsigned int u32;

#define NTOK 64
#define NHEAD 8
#define PSA_SCALE 0.17677669529663687f
#define NWIN 4096

// ---------------------------------------------------------------------------
// Device scratch
// ---------------------------------------------------------------------------
__device__ float4 g_qkv4[(size_t)NWIN * NTOK * 384 / 4];   // 402 MB qkv fp32
__device__ __half g_w1h[384 * 256];                        // fp16 split weights
__device__ __half g_w1l[384 * 256];                        // (unused this round)
__device__ __half g_w2h[256 * 128];
__device__ float  g_b1[384];
__device__ float  g_cmb[64 * NHEAD * NTOK * NTOK];         // bias+mask combined

// ---------------------------------------------------------------------------
// Helpers
// ---------------------------------------------------------------------------
__device__ __forceinline__ u32 smem_u32(const void* p) {
    u32 a;
    asm("{ .reg .u64 t; cvta.to.shared.u64 t, %1; cvt.u32.u64 %0, t; }"
        : "=r"(a) : "l"(p));
    return a;
}
__device__ __forceinline__ void ldsm4(u32* r, u32 addr) {
    asm volatile("ldmatrix.sync.aligned.m8n8.x4.shared.b16 {%0,%1,%2,%3}, [%4];"
                 : "=r"(r[0]), "=r"(r[1]), "=r"(r[2]), "=r"(r[3]) : "r"(addr));
}
__device__ __forceinline__ void mma_fp16(float* c, const u32* a, const u32* b) {
    asm volatile(
        "mma.sync.aligned.m16n8k16.row.col.f32.f16.f16.f32 "
        "{%0,%1,%2,%3}, {%4,%5,%6,%7}, {%8,%9}, {%0,%1,%2,%3};"
        : "+f"(c[0]), "+f"(c[1]), "+f"(c[2]), "+f"(c[3])
        : "r"(a[0]), "r"(a[1]), "r"(a[2]), "r"(a[3]), "r"(b[0]), "r"(b[1]));
}
#define CP_ASYNC16(dst, src) \
    asm volatile("cp.async.cg.shared.global [%0], [%1], 16;" :: "r"(dst), "l"(src))
#define CP_COMMIT() asm volatile("cp.async.commit_group;")
#define CP_WAIT(n)  asm volatile("cp.async.wait_group %0;" :: "n"(n))

__device__ __forceinline__ u32 h2u(__half2 v) { return *reinterpret_cast<u32*>(&v); }

__device__ __forceinline__ u64 pk2(float lo, float hi) {
    u64 r; asm("mov.b64 %0, {%1,%2};" : "=l"(r) : "f"(lo), "f"(hi)); return r;
}
__device__ __forceinline__ float2 upk2(u64 v) {
    float2 r; asm("mov.b64 {%0,%1}, %2;" : "=f"(r.x), "=f"(r.y) : "l"(v)); return r;
}
__device__ __forceinline__ void fma2(u64& d, u64 a, u64 b) {
    asm("fma.rn.f32x2 %0, %1, %2, %0;" : "+l"(d) : "l"(a), "l"(b));
}

// ---------------------------------------------------------------------------
// Prologue kernels
// ---------------------------------------------------------------------------
__global__ void psa_prep_w1(const float* __restrict__ qw,
                            const float* __restrict__ kvw) {
    int n = blockIdx.x, k = threadIdx.x;            // 384 x 256
    float v = (n < 128) ? qw[n * 256 + k] : kvw[(n - 128) * 256 + k];
    __half h = __float2half_rn(v);
    __half l = __float2half_rn(v - __half2float(h));
    g_w1h[n * 256 + k] = h;
    g_w1l[n * 256 + k] = l;
}
__global__ void psa_prep_w2(const float* __restrict__ pw) {
    int n = blockIdx.x, k = threadIdx.x;            // 256 x 128
    g_w2h[n * 128 + k] = __float2half_rn(pw[n * 128 + k]);
}
__global__ void psa_prep_b1(const float* __restrict__ qb,
                            const float* __restrict__ kvb) {
    int i = threadIdx.x;
    g_b1[i] = (i < 128) ? qb[i] : kvb[i - 128];
}
__global__ void psa_prep_cmb(const float* __restrict__ bt,
                             const int* __restrict__ ri,
                             const float* __restrict__ mask) {
    int idx = blockIdx.x * 512 + threadIdx.x;       // 2M elements
    int j = idx & 63, i = (idx >> 6) & 63, h = (idx >> 12) & 7, nw = idx >> 15;
    g_cmb[idx] = bt[ri[i * 64 + j] * NHEAD + h] + mask[nw * 4096 + i * 64 + j];
}

// ---------------------------------------------------------------------------
// GEMM1: qkv[M,384] = x[M,256] @ W1[384,256]^T + b1
// A = Ah+Al fp16 (exact 2-term), W single fp16. CTA M=128, 256 thr,
// 6 N-chunks of 64, cp.async double-buffered W.
// W chunk = 64 rows x 256 halves = 512 B/row = 32 uint4/row, 2048 uint4 total.
// ---------------------------------------------------------------------------
#define PK1     264                    // padded pitch (halves) for K=256
#define OFF_AL1 (128 * PK1 * 2)        // 67584
#define OFF_W1  (2 * 128 * PK1 * 2)    // 135168
#define WBUF1   (64 * PK1 * 2)         // 33792
#define SMEM_G1 (OFF_W1 + 2 * WBUF1)   // 202752

__global__ void __launch_bounds__(256, 1) psa_gemm1(
    const float* __restrict__ A,
    const __half* __restrict__ Whg,
    const float* __restrict__ bias,
    float* __restrict__ out)
{
    extern __shared__ char smem[];
    const u32 sb = smem_u32(smem);
    const int t = threadIdx.x, lane = t & 31, wid = t >> 5;
    const int m0 = (wid & 3) * 32, n0 = (wid >> 2) * 32;

    // kick off W chunk 0 prefetch (row = i>>5, 32 uint4 per row)
    {
        const uint4* gsrc = (const uint4*)Whg;
#pragma unroll
        for (int i = t; i < 2048; i += 256)
            CP_ASYNC16(sb + OFF_W1 + (i >> 5) * (PK1 * 2) + (i & 31) * 16, gsrc + i);
        CP_COMMIT();
    }

    // ---- convert A tile (128 x 256 fp32) -> Ah/Al fp16 ----
    {
        const float* Ag = A + (size_t)blockIdx.x * 128 * 256;
#pragma unroll 4
        for (int u = t; u < 128 * 32; u += 256) {
            int r = u >> 5, k0 = (u & 31) * 8;
            float4 a = *(const float4*)(Ag + r * 256 + k0);
            float4 b = *(const float4*)(Ag + r * 256 + k0 + 4);
            __half2 h0 = __float22half2_rn(make_float2(a.x, a.y));
            __half2 h1 = __float22half2_rn(make_float2(a.z, a.w));
            __half2 h2 = __float22half2_rn(make_float2(b.x, b.y));
            __half2 h3 = __float22half2_rn(make_float2(b.z, b.w));
            float2 f0 = __half22float2(h0), f1 = __half22float2(h1);
            float2 f2 = __half22float2(h2), f3 = __half22float2(h3);
            __half2 l0 = __float22half2_rn(make_float2(a.x - f0.x, a.y - f0.y));
            __half2 l1 = __float22half2_rn(make_float2(a.z - f1.x, a.w - f1.y));
            __half2 l2 = __float22half2_rn(make_float2(b.x - f2.x, b.y - f2.y));
            __half2 l3 = __float22half2_rn(make_float2(b.z - f3.x, b.w - f3.y));
            int off = r * (PK1 * 2) + k0 * 2;
            *(uint4*)(smem + off)           = make_uint4(h2u(h0), h2u(h1), h2u(h2), h2u(h3));
            *(uint4*)(smem + OFF_AL1 + off) = make_uint4(h2u(l0), h2u(l1), h2u(l2), h2u(l3));
        }
    }

    // per-lane ldmatrix offsets
    u32 a_off[2], w_off[2];
#pragma unroll
    for (int mi = 0; mi < 2; mi++)
        a_off[mi] = (u32)((m0 + mi * 16 + (lane & 15)) * (PK1 * 2) + (lane >> 4) * 16);
    {
        int brow = ((lane >> 4) & 1) * 8 + (lane & 7);
        int bko  = ((lane >> 3) & 1) * 16;
#pragma unroll
        for (int nj = 0; nj < 2; nj++)
            w_off[nj] = (u32)((n0 + nj * 16 + brow) * (PK1 * 2) + bko);
    }

#pragma unroll 1
    for (int ch = 0; ch < 6; ch++) {
        if (ch + 1 < 6) {   // prefetch next W chunk into the other buffer
            const uint4* gsrc = (const uint4*)(Whg + (size_t)(ch + 1) * 64 * 256);
            u32 dbase = sb + OFF_W1 + ((ch + 1) & 1) * WBUF1;
#pragma unroll
            for (int i = t; i < 2048; i += 256)
                CP_ASYNC16(dbase + (i >> 5) * (PK1 * 2) + (i & 31) * 16, gsrc + i);
            CP_COMMIT();
            CP_WAIT(1);
        } else {
            CP_WAIT(0);
        }
        __syncthreads();

        const u32 wb = sb + OFF_W1 + (ch & 1) * WBUF1;

        float c[2][4][4];
#pragma unroll
        for (int ni = 0; ni < 4; ni++) {
            int col = ch * 64 + n0 + ni * 8 + (lane & 3) * 2;
            float b0 = __ldg(bias + col), b1 = __ldg(bias + col + 1);
#pragma unroll
            for (int mi = 0; mi < 2; mi++) {
                c[mi][ni][0] = b0; c[mi][ni][1] = b1;
                c[mi][ni][2] = b0; c[mi][ni][3] = b1;
            }
        }

#pragma unroll 2
        for (int k0 = 0; k0 < 256; k0 += 16) {
            u32 ah[2][4], al[2][4], wf[2][4];
#pragma unroll
            for (int mi = 0; mi < 2; mi++) {
                ldsm4(ah[mi], sb + a_off[mi] + k0 * 2);
                ldsm4(al[mi], sb + OFF_AL1 + a_off[mi] + k0 * 2);
            }
#pragma unroll
            for (int nj = 0; nj < 2; nj++)
                ldsm4(wf[nj], wb + w_off[nj] + k0 * 2);
#pragma unroll
            for (int mi = 0; mi < 2; mi++)
#pragma unroll
                for (int nt = 0; nt < 4; nt++) {
                    mma_fp16(c[mi][nt], ah[mi], &wf[nt >> 1][(nt & 1) * 2]);
                    mma_fp16(c[mi][nt], al[mi], &wf[nt >> 1][(nt & 1) * 2]);
                }
        }
        __syncthreads();   // all warps done with buf[ch&1] before it is re-filled

        // direct frag stores to qkv scratch
        {
            int rq = lane >> 2, cq = (lane & 3) * 2;
            float* ob = out + (size_t)blockIdx.x * 128 * 384 + ch * 64;
#pragma unroll
            for (int mi = 0; mi < 2; mi++)
#pragma unroll
                for (int ni = 0; ni < 4; ni++) {
                    int rr = m0 + mi * 16 + rq, cc = n0 + ni * 8 + cq;
                    *(float2*)(ob + rr * 384 + cc)       = make_float2(c[mi][ni][0], c[mi][ni][1]);
                    *(float2*)(ob + (rr + 8) * 384 + cc) = make_float2(c[mi][ni][2], c[mi][ni][3]);
                }
        }
    }
}

// ---------------------------------------------------------------------------
// Fused attention + out-projection. One window per CTA, 512 threads.
// smem: R1 = qs[64][132] | ks[8][64][16] | vs[8][64][16]   (99328 B)
//            (reused after attention as aoh[64][136] | aol[64][136])
//       W2h [256][136] fp16                                (69632 B)
// W2 = 256 rows x 128 halves = 256 B/row = 16 uint4/row, 4096 uint4 total.
// ---------------------------------------------------------------------------
#define PA2     136
#define OFF_AOL (64 * PA2 * 2)             // 17408
#define OFF_W2  99328
#define SMEM_F  (OFF_W2 + 256 * PA2 * 2)   // 168960

__global__ void __launch_bounds__(512, 1) psa_attn_proj(
    const float4* __restrict__ qkvg, const float* __restrict__ cmbg,
    const __half* __restrict__ W2h,  const float* __restrict__ pb,
    float* __restrict__ out)
{
    extern __shared__ float sm[];
    float* qs = sm;            // [64][132]
    float* ks = sm + 8448;     // [8][64][16]
    float* vs = ks + 8192;     // [8][64][16]
    const u32 sb = smem_u32(sm);
    const int t = threadIdx.x, w = blockIdx.x;
    const int lane = t & 31, wid = t >> 5;

    // ---- prefetch full W2 (fp16) into smem via cp.async ----
    {
        const uint4* gsrc = (const uint4*)W2h;   // 4096 uint4
#pragma unroll
        for (int i = t; i < 4096; i += 512)
            CP_ASYNC16(sb + OFF_W2 + (i >> 4) * (PA2 * 2) + (i & 15) * 16, gsrc + i);
        CP_COMMIT();
    }

    // ---- stage qkv tile ----
    {
        const float4* qg = qkvg + (size_t)w * (NTOK * 384 / 4);
#pragma unroll
        for (int i = 0; i < 12; i++) {
            int idx = t + 512 * i;
            int row = idx / 96, c = (idx % 96) * 4;
            float4 v = qg[idx];
            if (c < 128) {
                *(float4*)&qs[row * 132 + c] = v;
            } else if (c < 256) {
                int cc = c - 128;
                *(float4*)&ks[(cc >> 4) * 1024 + row * 16 + (cc & 15)] = v;
            } else {
                int cc = c - 256;
                *(float4*)&vs[(cc >> 4) * 1024 + row * 16 + (cc & 15)] = v;
            }
        }
    }
    __syncthreads();

    const int h    = t >> 6;
    const int irow = ((t >> 5) & 1) * 32 + lane;

    u64 q2[8];
    {
        const float* qrow = &qs[irow * 132 + h * 16];
#pragma unroll
        for (int e = 0; e < 8; e++) q2[e] = *(const u64*)&qrow[2 * e];
    }

    float attn[64];
    const float* kh = ks + h * 1024;
#pragma unroll
    for (int jj = 0; jj < 64; jj++) {
        const float* krow = kh + jj * 16;
        u64 a2 = pk2(0.f, 0.f);
#pragma unroll
        for (int e = 0; e < 8; e++) fma2(a2, q2[e], *(const u64*)&krow[2 * e]);
        float2 f = upk2(a2);
        attn[jj] = f.x + f.y;
    }

    const float4* cb = (const float4*)(cmbg + ((((w & 63) * 8 + h) * 64 + irow) << 6));
    float mx = -3.0e38f;
#pragma unroll
    for (int q4 = 0; q4 < 16; q4++) {
        float4 b4 = __ldg(cb + q4);
        float v0 = attn[q4 * 4 + 0] * PSA_SCALE + b4.x;
        float v1 = attn[q4 * 4 + 1] * PSA_SCALE + b4.y;
        float v2 = attn[q4 * 4 + 2] * PSA_SCALE + b4.z;
        float v3 = attn[q4 * 4 + 3] * PSA_SCALE + b4.w;
        attn[q4 * 4 + 0] = v0; attn[q4 * 4 + 1] = v1;
        attn[q4 * 4 + 2] = v2; attn[q4 * 4 + 3] = v3;
        mx = fmaxf(mx, fmaxf(fmaxf(v0, v1), fmaxf(v2, v3)));
    }
    float s = 0.f;
#pragma unroll
    for (int jj = 0; jj < 64; jj++) {
        float e = __expf(attn[jj] - mx);
        attn[jj] = e;
        s += e;
    }
    float inv = 1.0f / s;

    u64 o2[8];
#pragma unroll
    for (int e = 0; e < 8; e++) o2[e] = pk2(0.f, 0.f);
    const float* vh = vs + h * 1024;
#pragma unroll
    for (int jj = 0; jj < 64; jj++) {
        float p = attn[jj] * inv;
        u64 p2 = pk2(p, p);
        const float* vrow = vh + jj * 16;
#pragma unroll
        for (int e = 0; e < 8; e++) fma2(o2[e], p2, *(const u64*)&vrow[2 * e]);
    }
    __syncthreads();   // all q/k/v reads done; R1 becomes ao region

    // ---- ao -> fp16 hi/lo in smem (exact 2-term split) ----
    {
        u32 hh[8], ll[8];
#pragma unroll
        for (int e = 0; e < 8; e++) {
            float2 f = upk2(o2[e]);
            __half2 hv = __float22half2_rn(f);
            float2 fr = __half22float2(hv);
            __half2 lv = __float22half2_rn(make_float2(f.x - fr.x, f.y - fr.y));
            hh[e] = h2u(hv); ll[e] = h2u(lv);
        }
        u32 ab = sb + irow * (PA2 * 2) + h * 32;
        asm volatile("st.shared.v4.b32 [%0], {%1,%2,%3,%4};" :: "r"(ab),
                     "r"(hh[0]), "r"(hh[1]), "r"(hh[2]), "r"(hh[3]));
        asm volatile("st.shared.v4.b32 [%0], {%1,%2,%3,%4};" :: "r"(ab + 16),
                     "r"(hh[4]), "r"(hh[5]), "r"(hh[6]), "r"(hh[7]));
        asm volatile("st.shared.v4.b32 [%0], {%1,%2,%3,%4};" :: "r"(ab + OFF_AOL),
                     "r"(ll[0]), "r"(ll[1]), "r"(ll[2]), "r"(ll[3]));
        asm volatile("st.shared.v4.b32 [%0], {%1,%2,%3,%4};" :: "r"(ab + OFF_AOL + 16),
                     "r"(ll[4]), "r"(ll[5]), "r"(ll[6]), "r"(ll[7]));
    }
    CP_WAIT(0);
    __syncthreads();

    // ---- GEMM2: out[64,256] = ao[64,128] @ W2^T + pb ----
    {
        const int m0 = (wid >> 2) * 16;
        const int n0 = (wid & 3) * 64;
        u32 a_off = (u32)((m0 + (lane & 15)) * (PA2 * 2) + (lane >> 4) * 16);
        u32 w_off[4];
        {
            int brow = ((lane >> 4) & 1) * 8 + (lane & 7);
            int bko  = ((lane >> 3) & 1) * 16;
#pragma unroll
            for (int nj = 0; nj < 4; nj++)
                w_off[nj] = (u32)(OFF_W2 + (n0 + nj * 16 + brow) * (PA2 * 2) + bko);
        }

        float c[8][4];
#pragma unroll
        for (int nt = 0; nt < 8; nt++) {
            int col = n0 + nt * 8 + (lane & 3) * 2;
            float b0 = __ldg(pb + col), b1 = __ldg(pb + col + 1);
            c[nt][0] = b0; c[nt][1] = b1; c[nt][2] = b0; c[nt][3] = b1;
        }

#pragma unroll 2
        for (int k0 = 0; k0 < 128; k0 += 16) {
            u32 ah[4], al[4], wf[4][4];
            ldsm4(ah, sb + a_off + k0 * 2);
            ldsm4(al, sb + OFF_AOL + a_off + k0 * 2);
#pragma unroll
            for (int nj = 0; nj < 4; nj++)
                ldsm4(wf[nj], sb + w_off[nj] + k0 * 2);
#pragma unroll
            for (int nt = 0; nt < 8; nt++) {
                mma_fp16(c[nt], ah, &wf[nt >> 1][(nt & 1) * 2]);
                mma_fp16(c[nt], al, &wf[nt >> 1][(nt & 1) * 2]);
            }
        }

        int rq = lane >> 2, cq = (lane & 3) * 2;
        float* ob = out + (size_t)w * 64 * 256;
#pragma unroll
        for (int nt = 0; nt < 8; nt++) {
            int rr = m0 + rq, cc = n0 + nt * 8 + cq;
            *(float2*)(ob + rr * 256 + cc)       = make_float2(c[nt][0], c[nt][1]);
            *(float2*)(ob + (rr + 8) * 256 + cc) = make_float2(c[nt][2], c[nt][3]);
        }
    }
}

// ---------------------------------------------------------------------------
extern "C" void kernel_launch(void* const* d_in, const int* in_sizes, int n_in,
                              void* d_out, int out_size) {
    const float* x      = (const float*)d_in[0];
    const float* mask   = (const float*)d_in[1];
    const float* q_w    = (const float*)d_in[2];
    const float* q_b    = (const float*)d_in[3];
    const float* kv_w   = (const float*)d_in[4];
    const float* kv_b   = (const float*)d_in[5];
    const float* proj_w = (const float*)d_in[6];
    const float* proj_b = (const float*)d_in[7];
    const float* bt     = (const float*)d_in[8];
    const int*   ri     = (const int*)d_in[9];
    float* out = (float*)d_out;

    void *pqkv, *pw1h, *pw2h, *pb1, *pcmb;
    cudaGetSymbolAddress(&pqkv, g_qkv4);
    cudaGetSymbolAddress(&pw1h, g_w1h);
    cudaGetSymbolAddress(&pw2h, g_w2h);
    cudaGetSymbolAddress(&pb1,  g_b1);
    cudaGetSymbolAddress(&pcmb, g_cmb);

    cudaFuncSetAttribute(psa_gemm1,
                         cudaFuncAttributeMaxDynamicSharedMemorySize, SMEM_G1);
    cudaFuncSetAttribute(psa_attn_proj,
                         cudaFuncAttributeMaxDynamicSharedMemorySize, SMEM_F);

    psa_prep_w1<<<384, 256>>>(q_w, kv_w);
    psa_prep_w2<<<256, 128>>>(proj_w);
    psa_prep_b1<<<1, 384>>>(q_b, kv_b);
    psa_prep_cmb<<<4096, 512>>>(bt, ri, mask);

    // 1) qkv = x @ [q_w;kv_w]^T + b   (fp16 2-term split, tensor cores)
    psa_gemm1<<<2048, 256, SMEM_G1>>>(
        x, (const __half*)pw1h, (const float*)pb1, (float*)pqkv);

    // 2) fused attention + out-projection
    psa_attn_proj<<<4096, 512, SMEM_F>>>(
        (const float4*)pqkv, (const float*)pcmb,
        (const __half*)pw2h, proj_b, out);
}

// round 9
// speedup vs baseline: 5.4069x; 1.8252x over previous
#include <cuda_runtime.h>
#include <cuda_fp16.h>
#include <cstdint>

typedef unsigned long long u64;
typedef unsigned int u32;

#define NTOK 64
#define NHEAD 8
#define PSA_SCALE 0.17677669529663687f
#define NWIN 4096

// ---------------------------------------------------------------------------
// Device scratch
// ---------------------------------------------------------------------------
__device__ float4 g_qkv4[(size_t)NWIN * NTOK * 384 / 4];   // 402 MB qkv fp32
__device__ __half g_w1h[384 * 256];                        // fp16 weights
__device__ __half g_w2h[256 * 128];
__device__ float  g_b1[384];
__device__ float  g_cmb[64 * NHEAD * NTOK * NTOK];         // bias+mask combined

// ---------------------------------------------------------------------------
// Helpers
// ---------------------------------------------------------------------------
__device__ __forceinline__ u32 smem_u32(const void* p) {
    u32 a;
    asm("{ .reg .u64 t; cvta.to.shared.u64 t, %1; cvt.u32.u64 %0, t; }"
        : "=r"(a) : "l"(p));
    return a;
}
__device__ __forceinline__ void ldsm4(u32* r, u32 addr) {
    asm volatile("ldmatrix.sync.aligned.m8n8.x4.shared.b16 {%0,%1,%2,%3}, [%4];"
                 : "=r"(r[0]), "=r"(r[1]), "=r"(r[2]), "=r"(r[3]) : "r"(addr));
}
__device__ __forceinline__ void ldsm4t(u32* r, u32 addr) {
    asm volatile("ldmatrix.sync.aligned.m8n8.x4.trans.shared.b16 {%0,%1,%2,%3}, [%4];"
                 : "=r"(r[0]), "=r"(r[1]), "=r"(r[2]), "=r"(r[3]) : "r"(addr));
}
__device__ __forceinline__ void mma_fp16(float* c, const u32* a, const u32* b) {
    asm volatile(
        "mma.sync.aligned.m16n8k16.row.col.f32.f16.f16.f32 "
        "{%0,%1,%2,%3}, {%4,%5,%6,%7}, {%8,%9}, {%0,%1,%2,%3};"
        : "+f"(c[0]), "+f"(c[1]), "+f"(c[2]), "+f"(c[3])
        : "r"(a[0]), "r"(a[1]), "r"(a[2]), "r"(a[3]), "r"(b[0]), "r"(b[1]));
}
#define CP_ASYNC16(dst, src) \
    asm volatile("cp.async.cg.shared.global [%0], [%1], 16;" :: "r"(dst), "l"(src))
#define CP_COMMIT() asm volatile("cp.async.commit_group;")
#define CP_WAIT(n)  asm volatile("cp.async.wait_group %0;" :: "n"(n))

__device__ __forceinline__ u32 h2u(__half2 v) { return *reinterpret_cast<u32*>(&v); }
__device__ __forceinline__ u32 pkh(float a, float b) {
    return h2u(__float22half2_rn(make_float2(a, b)));
}

// ---------------------------------------------------------------------------
// Prologue kernels
// ---------------------------------------------------------------------------
__global__ void psa_prep_w1(const float* __restrict__ qw,
                            const float* __restrict__ kvw) {
    int n = blockIdx.x, k = threadIdx.x;            // 384 x 256
    float v = (n < 128) ? qw[n * 256 + k] : kvw[(n - 128) * 256 + k];
    g_w1h[n * 256 + k] = __float2half_rn(v);
}
__global__ void psa_prep_w2(const float* __restrict__ pw) {
    int n = blockIdx.x, k = threadIdx.x;            // 256 x 128
    g_w2h[n * 128 + k] = __float2half_rn(pw[n * 128 + k]);
}
__global__ void psa_prep_b1(const float* __restrict__ qb,
                            const float* __restrict__ kvb) {
    int i = threadIdx.x;
    g_b1[i] = (i < 128) ? qb[i] : kvb[i - 128];
}
__global__ void psa_prep_cmb(const float* __restrict__ bt,
                             const int* __restrict__ ri,
                             const float* __restrict__ mask) {
    int idx = blockIdx.x * 512 + threadIdx.x;       // 2M elements
    int j = idx & 63, i = (idx >> 6) & 63, h = (idx >> 12) & 7, nw = idx >> 15;
    g_cmb[idx] = bt[ri[i * 64 + j] * NHEAD + h] + mask[nw * 4096 + i * 64 + j];
}

// ---------------------------------------------------------------------------
// GEMM1: qkv[M,384] = x[M,256] @ W1[384,256]^T + b1  (single-term fp16)
// CTA M=128, 256 thr, 6 N-chunks of 64, cp.async double-buffered W.
// ---------------------------------------------------------------------------
#define PK1     264                    // padded pitch (halves) for K=256
#define OFF_W1  (128 * PK1 * 2)        // 67584 (A region before it)
#define WBUF1   (64 * PK1 * 2)         // 33792
#define SMEM_G1 (OFF_W1 + 2 * WBUF1)   // 135168

__global__ void __launch_bounds__(256, 1) psa_gemm1(
    const float* __restrict__ A,
    const __half* __restrict__ Whg,
    const float* __restrict__ bias,
    float* __restrict__ out)
{
    extern __shared__ char smem[];
    const u32 sb = smem_u32(smem);
    const int t = threadIdx.x, lane = t & 31, wid = t >> 5;
    const int m0 = (wid & 3) * 32, n0 = (wid >> 2) * 32;

    // kick off W chunk 0 prefetch (32 uint4 per 64-row chunk row)
    {
        const uint4* gsrc = (const uint4*)Whg;
#pragma unroll
        for (int i = t; i < 2048; i += 256)
            CP_ASYNC16(sb + OFF_W1 + (i >> 5) * (PK1 * 2) + (i & 31) * 16, gsrc + i);
        CP_COMMIT();
    }

    // ---- convert A tile (128 x 256 fp32) -> fp16 ----
    {
        const float* Ag = A + (size_t)blockIdx.x * 128 * 256;
#pragma unroll 4
        for (int u = t; u < 128 * 32; u += 256) {
            int r = u >> 5, k0 = (u & 31) * 8;
            float4 a = *(const float4*)(Ag + r * 256 + k0);
            float4 b = *(const float4*)(Ag + r * 256 + k0 + 4);
            *(uint4*)(smem + r * (PK1 * 2) + k0 * 2) = make_uint4(
                pkh(a.x, a.y), pkh(a.z, a.w), pkh(b.x, b.y), pkh(b.z, b.w));
        }
    }

    u32 a_off[2], w_off[2];
#pragma unroll
    for (int mi = 0; mi < 2; mi++)
        a_off[mi] = (u32)((m0 + mi * 16 + (lane & 15)) * (PK1 * 2) + (lane >> 4) * 16);
    {
        int brow = ((lane >> 4) & 1) * 8 + (lane & 7);
        int bko  = ((lane >> 3) & 1) * 16;
#pragma unroll
        for (int nj = 0; nj < 2; nj++)
            w_off[nj] = (u32)((n0 + nj * 16 + brow) * (PK1 * 2) + bko);
    }

#pragma unroll 1
    for (int ch = 0; ch < 6; ch++) {
        if (ch + 1 < 6) {
            const uint4* gsrc = (const uint4*)(Whg + (size_t)(ch + 1) * 64 * 256);
            u32 dbase = sb + OFF_W1 + ((ch + 1) & 1) * WBUF1;
#pragma unroll
            for (int i = t; i < 2048; i += 256)
                CP_ASYNC16(dbase + (i >> 5) * (PK1 * 2) + (i & 31) * 16, gsrc + i);
            CP_COMMIT();
            CP_WAIT(1);
        } else {
            CP_WAIT(0);
        }
        __syncthreads();

        const u32 wb = sb + OFF_W1 + (ch & 1) * WBUF1;

        float c[2][4][4];
#pragma unroll
        for (int ni = 0; ni < 4; ni++) {
            int col = ch * 64 + n0 + ni * 8 + (lane & 3) * 2;
            float b0 = __ldg(bias + col), b1 = __ldg(bias + col + 1);
#pragma unroll
            for (int mi = 0; mi < 2; mi++) {
                c[mi][ni][0] = b0; c[mi][ni][1] = b1;
                c[mi][ni][2] = b0; c[mi][ni][3] = b1;
            }
        }

#pragma unroll 4
        for (int k0 = 0; k0 < 256; k0 += 16) {
            u32 ah[2][4], wf[2][4];
#pragma unroll
            for (int mi = 0; mi < 2; mi++) ldsm4(ah[mi], sb + a_off[mi] + k0 * 2);
#pragma unroll
            for (int nj = 0; nj < 2; nj++) ldsm4(wf[nj], wb + w_off[nj] + k0 * 2);
#pragma unroll
            for (int mi = 0; mi < 2; mi++)
#pragma unroll
                for (int nt = 0; nt < 4; nt++)
                    mma_fp16(c[mi][nt], ah[mi], &wf[nt >> 1][(nt & 1) * 2]);
        }
        __syncthreads();

        {
            int rq = lane >> 2, cq = (lane & 3) * 2;
            float* ob = out + (size_t)blockIdx.x * 128 * 384 + ch * 64;
#pragma unroll
            for (int mi = 0; mi < 2; mi++)
#pragma unroll
                for (int ni = 0; ni < 4; ni++) {
                    int rr = m0 + mi * 16 + rq, cc = n0 + ni * 8 + cq;
                    *(float2*)(ob + rr * 384 + cc)       = make_float2(c[mi][ni][0], c[mi][ni][1]);
                    *(float2*)(ob + (rr + 8) * 384 + cc) = make_float2(c[mi][ni][2], c[mi][ni][3]);
                }
        }
    }
}

// ---------------------------------------------------------------------------
// Fused HMMA attention + out-projection. One window per CTA, 512 threads.
// smem bytes:
//   qkv16 [64][392] halves (q:0-127,k:128-255,v:256-383)   50176
//   aoh [64][136], aol [64][136] halves                    2x17408
//   W2  [256][136] halves                                  69632
// ---------------------------------------------------------------------------
#define PQ      392
#define B_AOH   50176
#define B_AOL   67584
#define B_W2    84992
#define PA2     136
#define SMEM_B  154624

__global__ void __launch_bounds__(512, 1) psa_attn_proj(
    const float4* __restrict__ qkvg, const float* __restrict__ cmbg,
    const __half* __restrict__ W2h,  const float* __restrict__ pb,
    float* __restrict__ out)
{
    extern __shared__ char smem[];
    const u32 sb = smem_u32(smem);
    const int t = threadIdx.x, w = blockIdx.x;
    const int lane = t & 31, wid = t >> 5;

    // ---- prefetch full W2 (fp16) into smem (16 uint4 per 128-half row) ----
    {
        const uint4* gsrc = (const uint4*)W2h;   // 4096 uint4
#pragma unroll
        for (int i = t; i < 4096; i += 512)
            CP_ASYNC16(sb + B_W2 + (i >> 4) * (PA2 * 2) + (i & 15) * 16, gsrc + i);
        CP_COMMIT();
    }

    // ---- stage qkv tile: fp32 gmem -> fp16 smem (pitch PQ halves) ----
    {
        const float4* qg = qkvg + (size_t)w * 6144;   // 64*384/4
#pragma unroll
        for (int i = 0; i < 6; i++) {
            int idx = t + 512 * i;                    // 3072 groups of 8 floats
            int row = idx / 48, g8 = idx % 48;
            float4 a = qg[idx * 2], b = qg[idx * 2 + 1];
            *(uint4*)(smem + row * (PQ * 2) + g8 * 16) = make_uint4(
                pkh(a.x, a.y), pkh(a.z, a.w), pkh(b.x, b.y), pkh(b.z, b.w));
        }
    }
    __syncthreads();

    // =====================================================================
    // Attention: head h = wid>>1; warp covers rows m0..m0+31 (2 passes of 16)
    // =====================================================================
    const int h  = wid >> 1;
    const int m0 = (wid & 1) * 32;
    const int ql = lane >> 2, qc = (lane & 3) * 2;   // frag row/col pieces
    const float* cmb_h = cmbg + (((w & 63) * 8 + h) * 64) * 64;

#pragma unroll 1
    for (int mi = 0; mi < 2; mi++) {
        const int rb = m0 + mi * 16;

        // Q a-frag (m16 x k16) from q cols h*16..h*16+15
        u32 qa[4];
        ldsm4(qa, sb + (rb + (lane & 15)) * (PQ * 2) + h * 32 + (lane >> 4) * 16);

        // K b-frags: 8 n-tiles (64 tokens), k = d16
        u32 kb[4][4];
        {
            int brow = ((lane >> 4) & 1) * 8 + (lane & 7);
            int bko  = ((lane >> 3) & 1) * 16;
#pragma unroll
            for (int nt2 = 0; nt2 < 4; nt2++)
                ldsm4(kb[nt2], sb + (nt2 * 16 + brow) * (PQ * 2)
                               + (128 + h * 16) * 2 + bko);
        }

        // S = Q K^T
        float c[8][4];
#pragma unroll
        for (int nj = 0; nj < 8; nj++) { c[nj][0]=0.f; c[nj][1]=0.f; c[nj][2]=0.f; c[nj][3]=0.f; }
#pragma unroll
        for (int nj = 0; nj < 8; nj++)
            mma_fp16(c[nj], qa, &kb[nj >> 1][(nj & 1) * 2]);

        // logits = S*scale + cmb; row-wise max via quad shfl
        const int r0 = rb + ql;
        const float* cr0 = cmb_h + r0 * 64;
        const float* cr1 = cmb_h + (r0 + 8) * 64;
        float mx0 = -3.0e38f, mx1 = -3.0e38f;
#pragma unroll
        for (int nj = 0; nj < 8; nj++) {
            int col = nj * 8 + qc;
            float2 b0 = __ldg((const float2*)(cr0 + col));
            float2 b1 = __ldg((const float2*)(cr1 + col));
            c[nj][0] = c[nj][0] * PSA_SCALE + b0.x;
            c[nj][1] = c[nj][1] * PSA_SCALE + b0.y;
            c[nj][2] = c[nj][2] * PSA_SCALE + b1.x;
            c[nj][3] = c[nj][3] * PSA_SCALE + b1.y;
            mx0 = fmaxf(mx0, fmaxf(c[nj][0], c[nj][1]));
            mx1 = fmaxf(mx1, fmaxf(c[nj][2], c[nj][3]));
        }
        mx0 = fmaxf(mx0, __shfl_xor_sync(0xffffffff, mx0, 1));
        mx0 = fmaxf(mx0, __shfl_xor_sync(0xffffffff, mx0, 2));
        mx1 = fmaxf(mx1, __shfl_xor_sync(0xffffffff, mx1, 1));
        mx1 = fmaxf(mx1, __shfl_xor_sync(0xffffffff, mx1, 2));

        float s0 = 0.f, s1 = 0.f;
#pragma unroll
        for (int nj = 0; nj < 8; nj++) {
            c[nj][0] = __expf(c[nj][0] - mx0);
            c[nj][1] = __expf(c[nj][1] - mx0);
            c[nj][2] = __expf(c[nj][2] - mx1);
            c[nj][3] = __expf(c[nj][3] - mx1);
            s0 += c[nj][0] + c[nj][1];
            s1 += c[nj][2] + c[nj][3];
        }
        s0 += __shfl_xor_sync(0xffffffff, s0, 1);
        s0 += __shfl_xor_sync(0xffffffff, s0, 2);
        s1 += __shfl_xor_sync(0xffffffff, s1, 1);
        s1 += __shfl_xor_sync(0xffffffff, s1, 2);
        float inv0 = 1.0f / s0, inv1 = 1.0f / s1;

        // O = P V  (P from c-frags, V via ldmatrix.trans)
        float o[2][4];
        o[0][0]=0.f;o[0][1]=0.f;o[0][2]=0.f;o[0][3]=0.f;
        o[1][0]=0.f;o[1][1]=0.f;o[1][2]=0.f;o[1][3]=0.f;
        {
            int vrow = ((lane >> 3) & 1) * 8 + (lane & 7);  // token within 16
            int vcol = (lane >> 4) * 8;                     // d half
#pragma unroll
            for (int kt = 0; kt < 4; kt++) {
                u32 pa[4], vb[4];
                pa[0] = pkh(c[2*kt][0]   * inv0, c[2*kt][1]   * inv0);
                pa[1] = pkh(c[2*kt][2]   * inv1, c[2*kt][3]   * inv1);
                pa[2] = pkh(c[2*kt+1][0] * inv0, c[2*kt+1][1] * inv0);
                pa[3] = pkh(c[2*kt+1][2] * inv1, c[2*kt+1][3] * inv1);
                ldsm4t(vb, sb + (kt * 16 + vrow) * (PQ * 2)
                            + (256 + h * 16 + vcol) * 2);
#pragma unroll
                for (int nt = 0; nt < 2; nt++)
                    mma_fp16(o[nt], pa, &vb[nt * 2]);
            }
        }

        // store O -> aoh/aol (exact fp16 2-term split)
#pragma unroll
        for (int nt = 0; nt < 2; nt++) {
            int d0 = h * 16 + nt * 8 + qc;
#pragma unroll
            for (int rh = 0; rh < 2; rh++) {
                float f0 = o[nt][rh * 2], f1 = o[nt][rh * 2 + 1];
                __half2 hv = __float22half2_rn(make_float2(f0, f1));
                float2 fr = __half22float2(hv);
                __half2 lv = __float22half2_rn(make_float2(f0 - fr.x, f1 - fr.y));
                u32 off = (u32)((r0 + rh * 8) * (PA2 * 2) + d0 * 2);
                *(u32*)(smem + B_AOH + off) = h2u(hv);
                *(u32*)(smem + B_AOL + off) = h2u(lv);
            }
        }
    }

    CP_WAIT(0);
    __syncthreads();

    // =====================================================================
    // GEMM2: out[64,256] = ao[64,128] @ W2^T + pb  (ao 2-term exact)
    // =====================================================================
    {
        const int m0g = (wid >> 2) * 16;
        const int n0g = (wid & 3) * 64;
        u32 a_off = (u32)(B_AOH + (m0g + (lane & 15)) * (PA2 * 2) + (lane >> 4) * 16);
        u32 al_off = a_off + (B_AOL - B_AOH);
        u32 w_off[4];
        {
            int brow = ((lane >> 4) & 1) * 8 + (lane & 7);
            int bko  = ((lane >> 3) & 1) * 16;
#pragma unroll
            for (int nj = 0; nj < 4; nj++)
                w_off[nj] = (u32)(B_W2 + (n0g + nj * 16 + brow) * (PA2 * 2) + bko);
        }

        float c[8][4];
#pragma unroll
        for (int nt = 0; nt < 8; nt++) {
            int col = n0g + nt * 8 + (lane & 3) * 2;
            float b0 = __ldg(pb + col), b1 = __ldg(pb + col + 1);
            c[nt][0] = b0; c[nt][1] = b1; c[nt][2] = b0; c[nt][3] = b1;
        }

#pragma unroll 2
        for (int k0 = 0; k0 < 128; k0 += 16) {
            u32 ah[4], al[4], wf[4][4];
            ldsm4(ah, sb + a_off + k0 * 2);
            ldsm4(al, sb + al_off + k0 * 2);
#pragma unroll
            for (int nj = 0; nj < 4; nj++)
                ldsm4(wf[nj], sb + w_off[nj] + k0 * 2);
#pragma unroll
            for (int nt = 0; nt < 8; nt++) {
                mma_fp16(c[nt], ah, &wf[nt >> 1][(nt & 1) * 2]);
                mma_fp16(c[nt], al, &wf[nt >> 1][(nt & 1) * 2]);
            }
        }

        int rq = lane >> 2, cq = (lane & 3) * 2;
        float* ob = out + (size_t)w * 64 * 256;
#pragma unroll
        for (int nt = 0; nt < 8; nt++) {
            int rr = m0g + rq, cc = n0g + nt * 8 + cq;
            *(float2*)(ob + rr * 256 + cc)       = make_float2(c[nt][0], c[nt][1]);
            *(float2*)(ob + (rr + 8) * 256 + cc) = make_float2(c[nt][2], c[nt][3]);
        }
    }
}

// ---------------------------------------------------------------------------
extern "C" void kernel_launch(void* const* d_in, const int* in_sizes, int n_in,
                              void* d_out, int out_size) {
    const float* x      = (const float*)d_in[0];
    const float* mask   = (const float*)d_in[1];
    const float* q_w    = (const float*)d_in[2];
    const float* q_b    = (const float*)d_in[3];
    const float* kv_w   = (const float*)d_in[4];
    const float* kv_b   = (const float*)d_in[5];
    const float* proj_w = (const float*)d_in[6];
    const float* proj_b = (const float*)d_in[7];
    const float* bt     = (const float*)d_in[8];
    const int*   ri     = (const int*)d_in[9];
    float* out = (float*)d_out;

    void *pqkv, *pw1h, *pw2h, *pb1, *pcmb;
    cudaGetSymbolAddress(&pqkv, g_qkv4);
    cudaGetSymbolAddress(&pw1h, g_w1h);
    cudaGetSymbolAddress(&pw2h, g_w2h);
    cudaGetSymbolAddress(&pb1,  g_b1);
    cudaGetSymbolAddress(&pcmb, g_cmb);

    cudaFuncSetAttribute(psa_gemm1,
                         cudaFuncAttributeMaxDynamicSharedMemorySize, SMEM_G1);
    cudaFuncSetAttribute(psa_attn_proj,
                         cudaFuncAttributeMaxDynamicSharedMemorySize, SMEM_B);

    psa_prep_w1<<<384, 256>>>(q_w, kv_w);
    psa_prep_w2<<<256, 128>>>(proj_w);
    psa_prep_b1<<<1, 384>>>(q_b, kv_b);
    psa_prep_cmb<<<4096, 512>>>(bt, ri, mask);

    // 1) qkv = x @ [q_w;kv_w]^T + b   (single-term fp16 HMMA)
    psa_gemm1<<<2048, 256, SMEM_G1>>>(
        x, (const __half*)pw1h, (const float*)pb1, (float*)pqkv);

    // 2) fused HMMA attention + out-projection
    psa_attn_proj<<<4096, 512, SMEM_B>>>(
        (const float4*)pqkv, (const float*)pcmb,
        (const __half*)pw2h, proj_b, out);
}

// round 12
// speedup vs baseline: 5.7431x; 1.0622x over previous
#include <cuda_runtime.h>
#include <cuda_fp16.h>
#include <cstdint>

typedef unsigned long long u64;
typedef unsigned int u32;

#define NTOK 64
#define NHEAD 8
#define PSA_SCALE 0.17677669529663687f
#define NWIN 4096

// ---------------------------------------------------------------------------
// Device scratch
// ---------------------------------------------------------------------------
__device__ __half g_qkvh[(size_t)NWIN * NTOK * 384];       // 201 MB qkv fp16
__device__ __half g_w1h[384 * 256];                        // fp16 weights
__device__ __half g_w2h[256 * 128];
__device__ float  g_b1[384];
__device__ float  g_cmb[64 * NHEAD * NTOK * NTOK];         // bias+mask combined

// ---------------------------------------------------------------------------
// Helpers
// ---------------------------------------------------------------------------
__device__ __forceinline__ u32 smem_u32(const void* p) {
    u32 a;
    asm("{ .reg .u64 t; cvta.to.shared.u64 t, %1; cvt.u32.u64 %0, t; }"
        : "=r"(a) : "l"(p));
    return a;
}
__device__ __forceinline__ void ldsm4(u32* r, u32 addr) {
    asm volatile("ldmatrix.sync.aligned.m8n8.x4.shared.b16 {%0,%1,%2,%3}, [%4];"
                 : "=r"(r[0]), "=r"(r[1]), "=r"(r[2]), "=r"(r[3]) : "r"(addr));
}
__device__ __forceinline__ void ldsm4t(u32* r, u32 addr) {
    asm volatile("ldmatrix.sync.aligned.m8n8.x4.trans.shared.b16 {%0,%1,%2,%3}, [%4];"
                 : "=r"(r[0]), "=r"(r[1]), "=r"(r[2]), "=r"(r[3]) : "r"(addr));
}
__device__ __forceinline__ void mma_fp16(float* c, const u32* a, const u32* b) {
    asm volatile(
        "mma.sync.aligned.m16n8k16.row.col.f32.f16.f16.f32 "
        "{%0,%1,%2,%3}, {%4,%5,%6,%7}, {%8,%9}, {%0,%1,%2,%3};"
        : "+f"(c[0]), "+f"(c[1]), "+f"(c[2]), "+f"(c[3])
        : "r"(a[0]), "r"(a[1]), "r"(a[2]), "r"(a[3]), "r"(b[0]), "r"(b[1]));
}
#define CP_ASYNC16(dst, src) \
    asm volatile("cp.async.cg.shared.global [%0], [%1], 16;" :: "r"(dst), "l"(src))
#define CP_COMMIT() asm volatile("cp.async.commit_group;")
#define CP_WAIT(n)  asm volatile("cp.async.wait_group %0;" :: "n"(n))

__device__ __forceinline__ u32 h2u(__half2 v) { return *reinterpret_cast<u32*>(&v); }
__device__ __forceinline__ u32 pkh(float a, float b) {
    return h2u(__float22half2_rn(make_float2(a, b)));
}

// ---------------------------------------------------------------------------
// Prologue kernels
// ---------------------------------------------------------------------------
__global__ void psa_prep_w1(const float* __restrict__ qw,
                            const float* __restrict__ kvw) {
    int n = blockIdx.x, k = threadIdx.x;            // 384 x 256
    float v = (n < 128) ? qw[n * 256 + k] : kvw[(n - 128) * 256 + k];
    g_w1h[n * 256 + k] = __float2half_rn(v);
}
__global__ void psa_prep_w2(const float* __restrict__ pw) {
    int n = blockIdx.x, k = threadIdx.x;            // 256 x 128
    g_w2h[n * 128 + k] = __float2half_rn(pw[n * 128 + k]);
}
__global__ void psa_prep_b1(const float* __restrict__ qb,
                            const float* __restrict__ kvb) {
    int i = threadIdx.x;
    g_b1[i] = (i < 128) ? qb[i] : kvb[i - 128];
}
__global__ void psa_prep_cmb(const float* __restrict__ bt,
                             const int* __restrict__ ri,
                             const float* __restrict__ mask) {
    int idx = blockIdx.x * 512 + threadIdx.x;       // 2M elements
    int j = idx & 63, i = (idx >> 6) & 63, h = (idx >> 12) & 7, nw = idx >> 15;
    g_cmb[idx] = bt[ri[i * 64 + j] * NHEAD + h] + mask[nw * 4096 + i * 64 + j];
}

// ---------------------------------------------------------------------------
// GEMM1: qkv16[M,384] = fp16( x[M,256] @ W1[384,256]^T + b1 )
// CTA M=128, 256 thr, 6 N-chunks of 64, cp.async double-buffered W.
// ---------------------------------------------------------------------------
#define PK1     264                    // padded pitch (halves) for K=256
#define OFF_W1  (128 * PK1 * 2)        // 67584 (A region before it)
#define WBUF1   (64 * PK1 * 2)         // 33792
#define SMEM_G1 (OFF_W1 + 2 * WBUF1)   // 135168

__global__ void __launch_bounds__(256, 1) psa_gemm1(
    const float* __restrict__ A,
    const __half* __restrict__ Whg,
    const float* __restrict__ bias,
    __half* __restrict__ out)
{
    extern __shared__ char smem[];
    const u32 sb = smem_u32(smem);
    const int t = threadIdx.x, lane = t & 31, wid = t >> 5;
    const int m0 = (wid & 3) * 32, n0 = (wid >> 2) * 32;

    // kick off W chunk 0 prefetch (32 uint4 per 64-row chunk row)
    {
        const uint4* gsrc = (const uint4*)Whg;
#pragma unroll
        for (int i = t; i < 2048; i += 256)
            CP_ASYNC16(sb + OFF_W1 + (i >> 5) * (PK1 * 2) + (i & 31) * 16, gsrc + i);
        CP_COMMIT();
    }

    // ---- convert A tile (128 x 256 fp32) -> fp16 ----
    {
        const float* Ag = A + (size_t)blockIdx.x * 128 * 256;
#pragma unroll 4
        for (int u = t; u < 128 * 32; u += 256) {
            int r = u >> 5, k0 = (u & 31) * 8;
            float4 a = *(const float4*)(Ag + r * 256 + k0);
            float4 b = *(const float4*)(Ag + r * 256 + k0 + 4);
            *(uint4*)(smem + r * (PK1 * 2) + k0 * 2) = make_uint4(
                pkh(a.x, a.y), pkh(a.z, a.w), pkh(b.x, b.y), pkh(b.z, b.w));
        }
    }

    u32 a_off[2], w_off[2];
#pragma unroll
    for (int mi = 0; mi < 2; mi++)
        a_off[mi] = (u32)((m0 + mi * 16 + (lane & 15)) * (PK1 * 2) + (lane >> 4) * 16);
    {
        int brow = ((lane >> 4) & 1) * 8 + (lane & 7);
        int bko  = ((lane >> 3) & 1) * 16;
#pragma unroll
        for (int nj = 0; nj < 2; nj++)
            w_off[nj] = (u32)((n0 + nj * 16 + brow) * (PK1 * 2) + bko);
    }

#pragma unroll 1
    for (int ch = 0; ch < 6; ch++) {
        if (ch + 1 < 6) {
            const uint4* gsrc = (const uint4*)(Whg + (size_t)(ch + 1) * 64 * 256);
            u32 dbase = sb + OFF_W1 + ((ch + 1) & 1) * WBUF1;
#pragma unroll
            for (int i = t; i < 2048; i += 256)
                CP_ASYNC16(dbase + (i >> 5) * (PK1 * 2) + (i & 31) * 16, gsrc + i);
            CP_COMMIT();
            CP_WAIT(1);
        } else {
            CP_WAIT(0);
        }
        __syncthreads();

        const u32 wb = sb + OFF_W1 + (ch & 1) * WBUF1;

        float c[2][4][4];
#pragma unroll
        for (int ni = 0; ni < 4; ni++) {
            int col = ch * 64 + n0 + ni * 8 + (lane & 3) * 2;
            float b0 = __ldg(bias + col), b1 = __ldg(bias + col + 1);
#pragma unroll
            for (int mi = 0; mi < 2; mi++) {
                c[mi][ni][0] = b0; c[mi][ni][1] = b1;
                c[mi][ni][2] = b0; c[mi][ni][3] = b1;
            }
        }

#pragma unroll 4
        for (int k0 = 0; k0 < 256; k0 += 16) {
            u32 ah[2][4], wf[2][4];
#pragma unroll
            for (int mi = 0; mi < 2; mi++) ldsm4(ah[mi], sb + a_off[mi] + k0 * 2);
#pragma unroll
            for (int nj = 0; nj < 2; nj++) ldsm4(wf[nj], wb + w_off[nj] + k0 * 2);
#pragma unroll
            for (int mi = 0; mi < 2; mi++)
#pragma unroll
                for (int nt = 0; nt < 4; nt++)
                    mma_fp16(c[mi][nt], ah[mi], &wf[nt >> 1][(nt & 1) * 2]);
        }
        __syncthreads();

        // fp16 epilogue: each lane stores half2 pairs straight from frags
        {
            int rq = lane >> 2, cq = (lane & 3) * 2;
            __half* ob = out + (size_t)blockIdx.x * 128 * 384 + ch * 64;
#pragma unroll
            for (int mi = 0; mi < 2; mi++)
#pragma unroll
                for (int ni = 0; ni < 4; ni++) {
                    int rr = m0 + mi * 16 + rq, cc = n0 + ni * 8 + cq;
                    *(u32*)(ob + rr * 384 + cc)       = pkh(c[mi][ni][0], c[mi][ni][1]);
                    *(u32*)(ob + (rr + 8) * 384 + cc) = pkh(c[mi][ni][2], c[mi][ni][3]);
                }
        }
    }
}

// ---------------------------------------------------------------------------
// Fused HMMA attention + out-projection. One window per CTA, 512 threads.
// smem bytes:
//   qkv16 [64][392] halves (q:0-127,k:128-255,v:256-383)   50176
//   aoh [64][136] halves                                   17408
//   W2  [256][136] halves                                  69632
// ---------------------------------------------------------------------------
#define PQ      392
#define B_AOH   50176
#define B_W2    67584
#define PA2     136
#define SMEM_B  137216

__global__ void __launch_bounds__(512, 1) psa_attn_proj(
    const __half* __restrict__ qkvg, const float* __restrict__ cmbg,
    const __half* __restrict__ W2h,  const float* __restrict__ pb,
    float* __restrict__ out)
{
    extern __shared__ char smem[];
    const u32 sb = smem_u32(smem);
    const int t = threadIdx.x, w = blockIdx.x;
    const int lane = t & 31, wid = t >> 5;

    // ---- group 0: qkv tile (fp16, 48 uint4 per 64-row, 3072 total) ----
    {
        const uint4* qg = (const uint4*)qkvg + (size_t)w * 64 * 48;
#pragma unroll
        for (int i = 0; i < 6; i++) {
            int idx = t + 512 * i;
            int row = idx / 48, g = idx % 48;
            CP_ASYNC16(sb + row * (PQ * 2) + g * 16, qg + idx);
        }
        CP_COMMIT();
    }
    // ---- group 1: full W2 (fp16, 16 uint4 per 128-half row) ----
    {
        const uint4* gsrc = (const uint4*)W2h;   // 4096 uint4
#pragma unroll
        for (int i = t; i < 4096; i += 512)
            CP_ASYNC16(sb + B_W2 + (i >> 4) * (PA2 * 2) + (i & 15) * 16, gsrc + i);
        CP_COMMIT();
    }
    CP_WAIT(1);        // qkv resident; W2 still streaming
    __syncthreads();

    // =====================================================================
    // Attention: head h = wid>>1; warp covers rows m0..m0+31 (2 passes of 16)
    // =====================================================================
    const int h  = wid >> 1;
    const int m0 = (wid & 1) * 32;
    const int ql = lane >> 2, qc = (lane & 3) * 2;
    const float* cmb_h = cmbg + (((w & 63) * 8 + h) * 64) * 64;

#pragma unroll 1
    for (int mi = 0; mi < 2; mi++) {
        const int rb = m0 + mi * 16;

        // Q a-frag (m16 x k16) from q cols h*16..h*16+15
        u32 qa[4];
        ldsm4(qa, sb + (rb + (lane & 15)) * (PQ * 2) + h * 32 + (lane >> 4) * 16);

        // K b-frags: 8 n-tiles (64 tokens), k = d16
        u32 kb[4][4];
        {
            int brow = ((lane >> 4) & 1) * 8 + (lane & 7);
            int bko  = ((lane >> 3) & 1) * 16;
#pragma unroll
            for (int nt2 = 0; nt2 < 4; nt2++)
                ldsm4(kb[nt2], sb + (nt2 * 16 + brow) * (PQ * 2)
                               + (128 + h * 16) * 2 + bko);
        }

        // S = Q K^T
        float c[8][4];
#pragma unroll
        for (int nj = 0; nj < 8; nj++) { c[nj][0]=0.f; c[nj][1]=0.f; c[nj][2]=0.f; c[nj][3]=0.f; }
#pragma unroll
        for (int nj = 0; nj < 8; nj++)
            mma_fp16(c[nj], qa, &kb[nj >> 1][(nj & 1) * 2]);

        // logits = S*scale + cmb; row-wise max via quad shfl
        const int r0 = rb + ql;
        const float* cr0 = cmb_h + r0 * 64;
        const float* cr1 = cmb_h + (r0 + 8) * 64;
        float mx0 = -3.0e38f, mx1 = -3.0e38f;
#pragma unroll
        for (int nj = 0; nj < 8; nj++) {
            int col = nj * 8 + qc;
            float2 b0 = __ldg((const float2*)(cr0 + col));
            float2 b1 = __ldg((const float2*)(cr1 + col));
            c[nj][0] = c[nj][0] * PSA_SCALE + b0.x;
            c[nj][1] = c[nj][1] * PSA_SCALE + b0.y;
            c[nj][2] = c[nj][2] * PSA_SCALE + b1.x;
            c[nj][3] = c[nj][3] * PSA_SCALE + b1.y;
            mx0 = fmaxf(mx0, fmaxf(c[nj][0], c[nj][1]));
            mx1 = fmaxf(mx1, fmaxf(c[nj][2], c[nj][3]));
        }
        mx0 = fmaxf(mx0, __shfl_xor_sync(0xffffffff, mx0, 1));
        mx0 = fmaxf(mx0, __shfl_xor_sync(0xffffffff, mx0, 2));
        mx1 = fmaxf(mx1, __shfl_xor_sync(0xffffffff, mx1, 1));
        mx1 = fmaxf(mx1, __shfl_xor_sync(0xffffffff, mx1, 2));

        float s0 = 0.f, s1 = 0.f;
#pragma unroll
        for (int nj = 0; nj < 8; nj++) {
            c[nj][0] = __expf(c[nj][0] - mx0);
            c[nj][1] = __expf(c[nj][1] - mx0);
            c[nj][2] = __expf(c[nj][2] - mx1);
            c[nj][3] = __expf(c[nj][3] - mx1);
            s0 += c[nj][0] + c[nj][1];
            s1 += c[nj][2] + c[nj][3];
        }
        s0 += __shfl_xor_sync(0xffffffff, s0, 1);
        s0 += __shfl_xor_sync(0xffffffff, s0, 2);
        s1 += __shfl_xor_sync(0xffffffff, s1, 1);
        s1 += __shfl_xor_sync(0xffffffff, s1, 2);
        float inv0 = 1.0f / s0, inv1 = 1.0f / s1;

        // O = P V  (P from c-frags, V via ldmatrix.trans)
        float o[2][4];
        o[0][0]=0.f;o[0][1]=0.f;o[0][2]=0.f;o[0][3]=0.f;
        o[1][0]=0.f;o[1][1]=0.f;o[1][2]=0.f;o[1][3]=0.f;
        {
            int vrow = ((lane >> 3) & 1) * 8 + (lane & 7);
            int vcol = (lane >> 4) * 8;
#pragma unroll
            for (int kt = 0; kt < 4; kt++) {
                u32 pa[4], vb[4];
                pa[0] = pkh(c[2*kt][0]   * inv0, c[2*kt][1]   * inv0);
                pa[1] = pkh(c[2*kt][2]   * inv1, c[2*kt][3]   * inv1);
                pa[2] = pkh(c[2*kt+1][0] * inv0, c[2*kt+1][1] * inv0);
                pa[3] = pkh(c[2*kt+1][2] * inv1, c[2*kt+1][3] * inv1);
                ldsm4t(vb, sb + (kt * 16 + vrow) * (PQ * 2)
                            + (256 + h * 16 + vcol) * 2);
#pragma unroll
                for (int nt = 0; nt < 2; nt++)
                    mma_fp16(o[nt], pa, &vb[nt * 2]);
            }
        }

        // store O -> aoh (single fp16 term)
#pragma unroll
        for (int nt = 0; nt < 2; nt++) {
            int d0 = h * 16 + nt * 8 + qc;
#pragma unroll
            for (int rh = 0; rh < 2; rh++) {
                u32 off = (u32)((r0 + rh * 8) * (PA2 * 2) + d0 * 2);
                *(u32*)(smem + B_AOH + off) = pkh(o[nt][rh * 2], o[nt][rh * 2 + 1]);
            }
        }
    }

    CP_WAIT(0);        // W2 resident
    __syncthreads();

    // =====================================================================
    // GEMM2: out[64,256] = ao[64,128] @ W2^T + pb  (single fp16 term)
    // =====================================================================
    {
        const int m0g = (wid >> 2) * 16;
        const int n0g = (wid & 3) * 64;
        u32 a_off = (u32)(B_AOH + (m0g + (lane & 15)) * (PA2 * 2) + (lane >> 4) * 16);
        u32 w_off[4];
        {
            int brow = ((lane >> 4) & 1) * 8 + (lane & 7);
            int bko  = ((lane >> 3) & 1) * 16;
#pragma unroll
            for (int nj = 0; nj < 4; nj++)
                w_off[nj] = (u32)(B_W2 + (n0g + nj * 16 + brow) * (PA2 * 2) + bko);
        }

        float c[8][4];
#pragma unroll
        for (int nt = 0; nt < 8; nt++) {
            int col = n0g + nt * 8 + (lane & 3) * 2;
            float b0 = __ldg(pb + col), b1 = __ldg(pb + col + 1);
            c[nt][0] = b0; c[nt][1] = b1; c[nt][2] = b0; c[nt][3] = b1;
        }

#pragma unroll 4
        for (int k0 = 0; k0 < 128; k0 += 16) {
            u32 ah[4], wf[4][4];
            ldsm4(ah, sb + a_off + k0 * 2);
#pragma unroll
            for (int nj = 0; nj < 4; nj++)
                ldsm4(wf[nj], sb + w_off[nj] + k0 * 2);
#pragma unroll
            for (int nt = 0; nt < 8; nt++)
                mma_fp16(c[nt], ah, &wf[nt >> 1][(nt & 1) * 2]);
        }

        int rq = lane >> 2, cq = (lane & 3) * 2;
        float* ob = out + (size_t)w * 64 * 256;
#pragma unroll
        for (int nt = 0; nt < 8; nt++) {
            int rr = m0g + rq, cc = n0g + nt * 8 + cq;
            *(float2*)(ob + rr * 256 + cc)       = make_float2(c[nt][0], c[nt][1]);
            *(float2*)(ob + (rr + 8) * 256 + cc) = make_float2(c[nt][2], c[nt][3]);
        }
    }
}

// ---------------------------------------------------------------------------
extern "C" void kernel_launch(void* const* d_in, const int* in_sizes, int n_in,
                              void* d_out, int out_size) {
    const float* x      = (const float*)d_in[0];
    const float* mask   = (const float*)d_in[1];
    const float* q_w    = (const float*)d_in[2];
    const float* q_b    = (const float*)d_in[3];
    const float* kv_w   = (const float*)d_in[4];
    const float* kv_b   = (const float*)d_in[5];
    const float* proj_w = (const float*)d_in[6];
    const float* proj_b = (const float*)d_in[7];
    const float* bt     = (const float*)d_in[8];
    const int*   ri     = (const int*)d_in[9];
    float* out = (float*)d_out;

    void *pqkv, *pw1h, *pw2h, *pb1, *pcmb;
    cudaGetSymbolAddress(&pqkv, g_qkvh);
    cudaGetSymbolAddress(&pw1h, g_w1h);
    cudaGetSymbolAddress(&pw2h, g_w2h);
    cudaGetSymbolAddress(&pb1,  g_b1);
    cudaGetSymbolAddress(&pcmb, g_cmb);

    cudaFuncSetAttribute(psa_gemm1,
                         cudaFuncAttributeMaxDynamicSharedMemorySize, SMEM_G1);
    cudaFuncSetAttribute(psa_attn_proj,
                         cudaFuncAttributeMaxDynamicSharedMemorySize, SMEM_B);

    psa_prep_w1<<<384, 256>>>(q_w, kv_w);
    psa_prep_w2<<<256, 128>>>(proj_w);
    psa_prep_b1<<<1, 384>>>(q_b, kv_b);
    psa_prep_cmb<<<4096, 512>>>(bt, ri, mask);

    // 1) qkv16 = fp16( x @ [q_w;kv_w]^T + b )   (fp16 HMMA)
    psa_gemm1<<<2048, 256, SMEM_G1>>>(
        x, (const __half*)pw1h, (const float*)pb1, (__half*)pqkv);

    // 2) fused HMMA attention + out-projection
    psa_attn_proj<<<4096, 512, SMEM_B>>>(
        (const __half*)pqkv, (const float*)pcmb,
        (const __half*)pw2h, proj_b, out);
}

// round 13
// speedup vs baseline: 6.2298x; 1.0847x over previous
#include <cuda_runtime.h>
#include <cuda_fp16.h>
#include <cstdint>

typedef unsigned long long u64;
typedef unsigned int u32;

#define NTOK 64
#define NHEAD 8
#define PSA_SCALE 0.17677669529663687f
#define NWIN 4096

// ---------------------------------------------------------------------------
// Device scratch
// ---------------------------------------------------------------------------
__device__ __half g_qkvh[(size_t)NWIN * NTOK * 384];       // 201 MB qkv fp16
__device__ __half g_w1h[384 * 256];                        // fp16 weights (q rows pre-scaled)
__device__ __half g_w2h[256 * 128];
__device__ float  g_b1[384];                               // q part pre-scaled
__device__ float  g_cmb[64 * NHEAD * NTOK * NTOK];         // bias+mask combined

// ---------------------------------------------------------------------------
// Helpers
// ---------------------------------------------------------------------------
__device__ __forceinline__ u32 smem_u32(const void* p) {
    u32 a;
    asm("{ .reg .u64 t; cvta.to.shared.u64 t, %1; cvt.u32.u64 %0, t; }"
        : "=r"(a) : "l"(p));
    return a;
}
__device__ __forceinline__ void ldsm4(u32* r, u32 addr) {
    asm volatile("ldmatrix.sync.aligned.m8n8.x4.shared.b16 {%0,%1,%2,%3}, [%4];"
                 : "=r"(r[0]), "=r"(r[1]), "=r"(r[2]), "=r"(r[3]) : "r"(addr));
}
__device__ __forceinline__ void ldsm4t(u32* r, u32 addr) {
    asm volatile("ldmatrix.sync.aligned.m8n8.x4.trans.shared.b16 {%0,%1,%2,%3}, [%4];"
                 : "=r"(r[0]), "=r"(r[1]), "=r"(r[2]), "=r"(r[3]) : "r"(addr));
}
__device__ __forceinline__ void mma_fp16(float* c, const u32* a, const u32* b) {
    asm volatile(
        "mma.sync.aligned.m16n8k16.row.col.f32.f16.f16.f32 "
        "{%0,%1,%2,%3}, {%4,%5,%6,%7}, {%8,%9}, {%0,%1,%2,%3};"
        : "+f"(c[0]), "+f"(c[1]), "+f"(c[2]), "+f"(c[3])
        : "r"(a[0]), "r"(a[1]), "r"(a[2]), "r"(a[3]), "r"(b[0]), "r"(b[1]));
}
#define CP_ASYNC16(dst, src) \
    asm volatile("cp.async.cg.shared.global [%0], [%1], 16;" :: "r"(dst), "l"(src))
#define CP_COMMIT() asm volatile("cp.async.commit_group;")
#define CP_WAIT(n)  asm volatile("cp.async.wait_group %0;" :: "n"(n))

__device__ __forceinline__ u32 h2u(__half2 v) { return *reinterpret_cast<u32*>(&v); }
__device__ __forceinline__ u32 pkh(float a, float b) {
    return h2u(__float22half2_rn(make_float2(a, b)));
}

// ---------------------------------------------------------------------------
// Prologue kernels
// ---------------------------------------------------------------------------
__global__ void psa_prep_w1(const float* __restrict__ qw,
                            const float* __restrict__ kvw) {
    int n = blockIdx.x, k = threadIdx.x;            // 384 x 256
    float v = (n < 128) ? qw[n * 256 + k] * PSA_SCALE   // fold attn scale into q
                        : kvw[(n - 128) * 256 + k];
    g_w1h[n * 256 + k] = __float2half_rn(v);
}
__global__ void psa_prep_w2(const float* __restrict__ pw) {
    int n = blockIdx.x, k = threadIdx.x;            // 256 x 128
    g_w2h[n * 128 + k] = __float2half_rn(pw[n * 128 + k]);
}
__global__ void psa_prep_b1(const float* __restrict__ qb,
                            const float* __restrict__ kvb) {
    int i = threadIdx.x;
    g_b1[i] = (i < 128) ? qb[i] * PSA_SCALE : kvb[i - 128];
}
__global__ void psa_prep_cmb(const float* __restrict__ bt,
                             const int* __restrict__ ri,
                             const float* __restrict__ mask) {
    int idx = blockIdx.x * 512 + threadIdx.x;       // 2M elements
    int j = idx & 63, i = (idx >> 6) & 63, h = (idx >> 12) & 7, nw = idx >> 15;
    g_cmb[idx] = bt[ri[i * 64 + j] * NHEAD + h] + mask[nw * 4096 + i * 64 + j];
}

// ---------------------------------------------------------------------------
// GEMM1: qkv16[M,384] = fp16( x[M,256] @ W1[384,256]^T + b1 )
// CTA M=128, 256 thr, 6 N-chunks of 64, cp.async double-buffered W.
// ---------------------------------------------------------------------------
#define PK1     264                    // padded pitch (halves) for K=256
#define OFF_W1  (128 * PK1 * 2)        // 67584
#define WBUF1   (64 * PK1 * 2)         // 33792
#define SMEM_G1 (OFF_W1 + 2 * WBUF1)   // 135168

__global__ void __launch_bounds__(256, 1) psa_gemm1(
    const float* __restrict__ A,
    const __half* __restrict__ Whg,
    const float* __restrict__ bias,
    __half* __restrict__ out)
{
    extern __shared__ char smem[];
    const u32 sb = smem_u32(smem);
    const int t = threadIdx.x, lane = t & 31, wid = t >> 5;
    const int m0 = (wid & 3) * 32, n0 = (wid >> 2) * 32;

    {
        const uint4* gsrc = (const uint4*)Whg;
#pragma unroll
        for (int i = t; i < 2048; i += 256)
            CP_ASYNC16(sb + OFF_W1 + (i >> 5) * (PK1 * 2) + (i & 31) * 16, gsrc + i);
        CP_COMMIT();
    }

    {
        const float* Ag = A + (size_t)blockIdx.x * 128 * 256;
#pragma unroll 4
        for (int u = t; u < 128 * 32; u += 256) {
            int r = u >> 5, k0 = (u & 31) * 8;
            float4 a = *(const float4*)(Ag + r * 256 + k0);
            float4 b = *(const float4*)(Ag + r * 256 + k0 + 4);
            *(uint4*)(smem + r * (PK1 * 2) + k0 * 2) = make_uint4(
                pkh(a.x, a.y), pkh(a.z, a.w), pkh(b.x, b.y), pkh(b.z, b.w));
        }
    }

    u32 a_off[2], w_off[2];
#pragma unroll
    for (int mi = 0; mi < 2; mi++)
        a_off[mi] = (u32)((m0 + mi * 16 + (lane & 15)) * (PK1 * 2) + (lane >> 4) * 16);
    {
        int brow = ((lane >> 4) & 1) * 8 + (lane & 7);
        int bko  = ((lane >> 3) & 1) * 16;
#pragma unroll
        for (int nj = 0; nj < 2; nj++)
            w_off[nj] = (u32)((n0 + nj * 16 + brow) * (PK1 * 2) + bko);
    }

#pragma unroll 1
    for (int ch = 0; ch < 6; ch++) {
        if (ch + 1 < 6) {
            const uint4* gsrc = (const uint4*)(Whg + (size_t)(ch + 1) * 64 * 256);
            u32 dbase = sb + OFF_W1 + ((ch + 1) & 1) * WBUF1;
#pragma unroll
            for (int i = t; i < 2048; i += 256)
                CP_ASYNC16(dbase + (i >> 5) * (PK1 * 2) + (i & 31) * 16, gsrc + i);
            CP_COMMIT();
            CP_WAIT(1);
        } else {
            CP_WAIT(0);
        }
        __syncthreads();

        const u32 wb = sb + OFF_W1 + (ch & 1) * WBUF1;

        float c[2][4][4];
#pragma unroll
        for (int ni = 0; ni < 4; ni++) {
            int col = ch * 64 + n0 + ni * 8 + (lane & 3) * 2;
            float b0 = __ldg(bias + col), b1 = __ldg(bias + col + 1);
#pragma unroll
            for (int mi = 0; mi < 2; mi++) {
                c[mi][ni][0] = b0; c[mi][ni][1] = b1;
                c[mi][ni][2] = b0; c[mi][ni][3] = b1;
            }
        }

#pragma unroll 4
        for (int k0 = 0; k0 < 256; k0 += 16) {
            u32 ah[2][4], wf[2][4];
#pragma unroll
            for (int mi = 0; mi < 2; mi++) ldsm4(ah[mi], sb + a_off[mi] + k0 * 2);
#pragma unroll
            for (int nj = 0; nj < 2; nj++) ldsm4(wf[nj], wb + w_off[nj] + k0 * 2);
#pragma unroll
            for (int mi = 0; mi < 2; mi++)
#pragma unroll
                for (int nt = 0; nt < 4; nt++)
                    mma_fp16(c[mi][nt], ah[mi], &wf[nt >> 1][(nt & 1) * 2]);
        }
        __syncthreads();

        {
            int rq = lane >> 2, cq = (lane & 3) * 2;
            __half* ob = out + (size_t)blockIdx.x * 128 * 384 + ch * 64;
#pragma unroll
            for (int mi = 0; mi < 2; mi++)
#pragma unroll
                for (int ni = 0; ni < 4; ni++) {
                    int rr = m0 + mi * 16 + rq, cc = n0 + ni * 8 + cq;
                    *(u32*)(ob + rr * 384 + cc)       = pkh(c[mi][ni][0], c[mi][ni][1]);
                    *(u32*)(ob + (rr + 8) * 384 + cc) = pkh(c[mi][ni][2], c[mi][ni][3]);
                }
        }
    }
}

// ---------------------------------------------------------------------------
// Fused HMMA attention + out-projection. One window per CTA, 256 threads,
// 2 CTAs/SM. One warp per head; K/V frags hoisted; W2 in a 128-row half-
// buffer reloaded between the two gemm2 N-halves.
// smem: qkv16 [64][392] (50176) | aoh [64][136] (17408) | W2buf [128][136] (34816)
// ---------------------------------------------------------------------------
#define PQ      392
#define B_AOH   50176
#define B_W2    67584
#define PA2     136
#define SMEM_B  102400

__global__ void __launch_bounds__(256, 2) psa_attn_proj(
    const __half* __restrict__ qkvg, const float* __restrict__ cmbg,
    const __half* __restrict__ W2h,  const float* __restrict__ pb,
    float* __restrict__ out)
{
    extern __shared__ char smem[];
    const u32 sb = smem_u32(smem);
    const int t = threadIdx.x, w = blockIdx.x;
    const int lane = t & 31, wid = t >> 5;

    // group 0: qkv tile (3072 uint4)
    {
        const uint4* qg = (const uint4*)qkvg + (size_t)w * 64 * 48;
#pragma unroll
        for (int i = 0; i < 12; i++) {
            int idx = t + 256 * i;
            int row = idx / 48, g = idx % 48;
            CP_ASYNC16(sb + row * (PQ * 2) + g * 16, qg + idx);
        }
        CP_COMMIT();
    }
    // group 1: W2 rows 0-127 into half-buffer (2048 uint4)
    {
        const uint4* gsrc = (const uint4*)W2h;
#pragma unroll
        for (int i = t; i < 2048; i += 256)
            CP_ASYNC16(sb + B_W2 + (i >> 4) * (PA2 * 2) + (i & 15) * 16, gsrc + i);
        CP_COMMIT();
    }
    CP_WAIT(1);        // qkv resident
    __syncthreads();

    // =====================================================================
    // Attention: one head per warp (h = wid), 4 passes of 16 rows
    // =====================================================================
    const int h  = wid;
    const int ql = lane >> 2, qc = (lane & 3) * 2;
    const float* cmb_h = cmbg + (((w & 63) * 8 + h) * 64) * 64;

    // K b-frags and V frags: pass-invariant, load once
    u32 kb[4][4], vb[4][4];
    {
        int brow = ((lane >> 4) & 1) * 8 + (lane & 7);
        int bko  = ((lane >> 3) & 1) * 16;
#pragma unroll
        for (int nt2 = 0; nt2 < 4; nt2++)
            ldsm4(kb[nt2], sb + (nt2 * 16 + brow) * (PQ * 2)
                           + (128 + h * 16) * 2 + bko);
        int vrow = ((lane >> 3) & 1) * 8 + (lane & 7);
        int vcol = (lane >> 4) * 8;
#pragma unroll
        for (int kt = 0; kt < 4; kt++)
            ldsm4t(vb[kt], sb + (kt * 16 + vrow) * (PQ * 2)
                           + (256 + h * 16 + vcol) * 2);
    }

#pragma unroll 1
    for (int mi = 0; mi < 4; mi++) {
        const int rb = mi * 16;

        u32 qa[4];
        ldsm4(qa, sb + (rb + (lane & 15)) * (PQ * 2) + h * 32 + (lane >> 4) * 16);

        // S = Q K^T  (scale pre-folded into q)
        float c[8][4];
#pragma unroll
        for (int nj = 0; nj < 8; nj++) { c[nj][0]=0.f; c[nj][1]=0.f; c[nj][2]=0.f; c[nj][3]=0.f; }
#pragma unroll
        for (int nj = 0; nj < 8; nj++)
            mma_fp16(c[nj], qa, &kb[nj >> 1][(nj & 1) * 2]);

        // logits = S + cmb; exp without max-shift (|logit| << 88)
        const int r0 = rb + ql;
        const float* cr0 = cmb_h + r0 * 64;
        const float* cr1 = cmb_h + (r0 + 8) * 64;
        float s0 = 0.f, s1 = 0.f;
#pragma unroll
        for (int nj = 0; nj < 8; nj++) {
            int col = nj * 8 + qc;
            float2 b0 = __ldg((const float2*)(cr0 + col));
            float2 b1 = __ldg((const float2*)(cr1 + col));
            c[nj][0] = __expf(c[nj][0] + b0.x);
            c[nj][1] = __expf(c[nj][1] + b0.y);
            c[nj][2] = __expf(c[nj][2] + b1.x);
            c[nj][3] = __expf(c[nj][3] + b1.y);
            s0 += c[nj][0] + c[nj][1];
            s1 += c[nj][2] + c[nj][3];
        }
        s0 += __shfl_xor_sync(0xffffffff, s0, 1);
        s0 += __shfl_xor_sync(0xffffffff, s0, 2);
        s1 += __shfl_xor_sync(0xffffffff, s1, 1);
        s1 += __shfl_xor_sync(0xffffffff, s1, 2);
        float inv0 = 1.0f / s0, inv1 = 1.0f / s1;

        // O = P V
        float o[2][4];
        o[0][0]=0.f;o[0][1]=0.f;o[0][2]=0.f;o[0][3]=0.f;
        o[1][0]=0.f;o[1][1]=0.f;o[1][2]=0.f;o[1][3]=0.f;
#pragma unroll
        for (int kt = 0; kt < 4; kt++) {
            u32 pa[4];
            pa[0] = pkh(c[2*kt][0]   * inv0, c[2*kt][1]   * inv0);
            pa[1] = pkh(c[2*kt][2]   * inv1, c[2*kt][3]   * inv1);
            pa[2] = pkh(c[2*kt+1][0] * inv0, c[2*kt+1][1] * inv0);
            pa[3] = pkh(c[2*kt+1][2] * inv1, c[2*kt+1][3] * inv1);
#pragma unroll
            for (int nt = 0; nt < 2; nt++)
                mma_fp16(o[nt], pa, &vb[kt][nt * 2]);
        }

        // store O -> aoh
#pragma unroll
        for (int nt = 0; nt < 2; nt++) {
            int d0 = h * 16 + nt * 8 + qc;
#pragma unroll
            for (int rh = 0; rh < 2; rh++) {
                u32 off = (u32)((r0 + rh * 8) * (PA2 * 2) + d0 * 2);
                *(u32*)(smem + B_AOH + off) = pkh(o[nt][rh * 2], o[nt][rh * 2 + 1]);
            }
        }
    }

    CP_WAIT(0);        // W2 half 0 resident
    __syncthreads();

    // =====================================================================
    // GEMM2: out[64,256] = ao[64,128] @ W2^T + pb, in two 128-col halves
    // =====================================================================
    const int m0g = (wid >> 1) * 16;
    const int n0g = (wid & 1) * 64;
    u32 a_off = (u32)(B_AOH + (m0g + (lane & 15)) * (PA2 * 2) + (lane >> 4) * 16);
    u32 w_off[4];
    {
        int brow = ((lane >> 4) & 1) * 8 + (lane & 7);
        int bko  = ((lane >> 3) & 1) * 16;
#pragma unroll
        for (int nj = 0; nj < 4; nj++)
            w_off[nj] = (u32)(B_W2 + (n0g + nj * 16 + brow) * (PA2 * 2) + bko);
    }
    int rq = lane >> 2, cq = (lane & 3) * 2;
    float* ob = out + (size_t)w * 64 * 256;

#pragma unroll 1
    for (int ph = 0; ph < 2; ph++) {
        float c[8][4];
#pragma unroll
        for (int nt = 0; nt < 8; nt++) {
            int col = ph * 128 + n0g + nt * 8 + cq;
            float b0 = __ldg(pb + col), b1 = __ldg(pb + col + 1);
            c[nt][0] = b0; c[nt][1] = b1; c[nt][2] = b0; c[nt][3] = b1;
        }

#pragma unroll 4
        for (int k0 = 0; k0 < 128; k0 += 16) {
            u32 ah[4], wf[4][4];
            ldsm4(ah, sb + a_off + k0 * 2);
#pragma unroll
            for (int nj = 0; nj < 4; nj++)
                ldsm4(wf[nj], sb + w_off[nj] + k0 * 2);
#pragma unroll
            for (int nt = 0; nt < 8; nt++)
                mma_fp16(c[nt], ah, &wf[nt >> 1][(nt & 1) * 2]);
        }

#pragma unroll
        for (int nt = 0; nt < 8; nt++) {
            int rr = m0g + rq, cc = ph * 128 + n0g + nt * 8 + cq;
            *(float2*)(ob + rr * 256 + cc)       = make_float2(c[nt][0], c[nt][1]);
            *(float2*)(ob + (rr + 8) * 256 + cc) = make_float2(c[nt][2], c[nt][3]);
        }

        if (ph == 0) {   // reload buffer with W2 rows 128-255
            __syncthreads();
            const uint4* gsrc = (const uint4*)W2h + 2048;
#pragma unroll
            for (int i = t; i < 2048; i += 256)
                CP_ASYNC16(sb + B_W2 + (i >> 4) * (PA2 * 2) + (i & 15) * 16, gsrc + i);
            CP_COMMIT();
            CP_WAIT(0);
            __syncthreads();
        }
    }
}

// ---------------------------------------------------------------------------
extern "C" void kernel_launch(void* const* d_in, const int* in_sizes, int n_in,
                              void* d_out, int out_size) {
    const float* x      = (const float*)d_in[0];
    const float* mask   = (const float*)d_in[1];
    const float* q_w    = (const float*)d_in[2];
    const float* q_b    = (const float*)d_in[3];
    const float* kv_w   = (const float*)d_in[4];
    const float* kv_b   = (const float*)d_in[5];
    const float* proj_w = (const float*)d_in[6];
    const float* proj_b = (const float*)d_in[7];
    const float* bt     = (const float*)d_in[8];
    const int*   ri     = (const int*)d_in[9];
    float* out = (float*)d_out;

    void *pqkv, *pw1h, *pw2h, *pb1, *pcmb;
    cudaGetSymbolAddress(&pqkv, g_qkvh);
    cudaGetSymbolAddress(&pw1h, g_w1h);
    cudaGetSymbolAddress(&pw2h, g_w2h);
    cudaGetSymbolAddress(&pb1,  g_b1);
    cudaGetSymbolAddress(&pcmb, g_cmb);

    cudaFuncSetAttribute(psa_gemm1,
                         cudaFuncAttributeMaxDynamicSharedMemorySize, SMEM_G1);
    cudaFuncSetAttribute(psa_attn_proj,
                         cudaFuncAttributeMaxDynamicSharedMemorySize, SMEM_B);

    psa_prep_w1<<<384, 256>>>(q_w, kv_w);
    psa_prep_w2<<<256, 128>>>(proj_w);
    psa_prep_b1<<<1, 384>>>(q_b, kv_b);
    psa_prep_cmb<<<4096, 512>>>(bt, ri, mask);

    // 1) qkv16 = fp16( x @ [q_w*scale;kv_w]^T + b )
    psa_gemm1<<<2048, 256, SMEM_G1>>>(
        x, (const __half*)pw1h, (const float*)pb1, (__half*)pqkv);

    // 2) fused HMMA attention + out-projection (2 CTAs/SM)
    psa_attn_proj<<<4096, 256, SMEM_B>>>(
        (const __half*)pqkv, (const float*)pcmb,
        (const __half*)pw2h, proj_b, out);
}

// round 14
// speedup vs baseline: 6.7982x; 1.0912x over previous
#include <cuda_runtime.h>
#include <cuda_fp16.h>
#include <cstdint>

typedef unsigned long long u64;
typedef unsigned int u32;

#define NTOK 64
#define NHEAD 8
#define PSA_SCALE 0.17677669529663687f
#define NWIN 4096

// ---------------------------------------------------------------------------
// Device scratch
// ---------------------------------------------------------------------------
__device__ __half g_qkvh[(size_t)NWIN * NTOK * 384];       // 201 MB qkv fp16
__device__ __half g_w1h[384 * 256];                        // fp16 weights (q rows pre-scaled)
__device__ __half g_w2h[256 * 128];
__device__ float  g_b1[384];                               // q part pre-scaled
__device__ float  g_cmb[64 * NHEAD * NTOK * NTOK];         // bias+mask combined

// ---------------------------------------------------------------------------
// Helpers
// ---------------------------------------------------------------------------
__device__ __forceinline__ u32 smem_u32(const void* p) {
    u32 a;
    asm("{ .reg .u64 t; cvta.to.shared.u64 t, %1; cvt.u32.u64 %0, t; }"
        : "=r"(a) : "l"(p));
    return a;
}
__device__ __forceinline__ void ldsm4(u32* r, u32 addr) {
    asm volatile("ldmatrix.sync.aligned.m8n8.x4.shared.b16 {%0,%1,%2,%3}, [%4];"
                 : "=r"(r[0]), "=r"(r[1]), "=r"(r[2]), "=r"(r[3]) : "r"(addr));
}
__device__ __forceinline__ void ldsm4t(u32* r, u32 addr) {
    asm volatile("ldmatrix.sync.aligned.m8n8.x4.trans.shared.b16 {%0,%1,%2,%3}, [%4];"
                 : "=r"(r[0]), "=r"(r[1]), "=r"(r[2]), "=r"(r[3]) : "r"(addr));
}
__device__ __forceinline__ void mma_fp16(float* c, const u32* a, const u32* b) {
    asm volatile(
        "mma.sync.aligned.m16n8k16.row.col.f32.f16.f16.f32 "
        "{%0,%1,%2,%3}, {%4,%5,%6,%7}, {%8,%9}, {%0,%1,%2,%3};"
        : "+f"(c[0]), "+f"(c[1]), "+f"(c[2]), "+f"(c[3])
        : "r"(a[0]), "r"(a[1]), "r"(a[2]), "r"(a[3]), "r"(b[0]), "r"(b[1]));
}
#define CP_ASYNC16(dst, src) \
    asm volatile("cp.async.cg.shared.global [%0], [%1], 16;" :: "r"(dst), "l"(src))
#define CP_COMMIT() asm volatile("cp.async.commit_group;")
#define CP_WAIT(n)  asm volatile("cp.async.wait_group %0;" :: "n"(n))

__device__ __forceinline__ u32 h2u(__half2 v) { return *reinterpret_cast<u32*>(&v); }
__device__ __forceinline__ u32 pkh(float a, float b) {
    return h2u(__float22half2_rn(make_float2(a, b)));
}

// ---------------------------------------------------------------------------
// Prologue kernels
// ---------------------------------------------------------------------------
__global__ void psa_prep_w1(const float* __restrict__ qw,
                            const float* __restrict__ kvw) {
    int n = blockIdx.x, k = threadIdx.x;            // 384 x 256
    float v = (n < 128) ? qw[n * 256 + k] * PSA_SCALE   // fold attn scale into q
                        : kvw[(n - 128) * 256 + k];
    g_w1h[n * 256 + k] = __float2half_rn(v);
}
__global__ void psa_prep_w2(const float* __restrict__ pw) {
    int n = blockIdx.x, k = threadIdx.x;            // 256 x 128
    g_w2h[n * 128 + k] = __float2half_rn(pw[n * 128 + k]);
}
__global__ void psa_prep_b1(const float* __restrict__ qb,
                            const float* __restrict__ kvb) {
    int i = threadIdx.x;
    g_b1[i] = (i < 128) ? qb[i] * PSA_SCALE : kvb[i - 128];
}
__global__ void psa_prep_cmb(const float* __restrict__ bt,
                             const int* __restrict__ ri,
                             const float* __restrict__ mask) {
    int idx = blockIdx.x * 512 + threadIdx.x;       // 2M elements
    int j = idx & 63, i = (idx >> 6) & 63, h = (idx >> 12) & 7, nw = idx >> 15;
    g_cmb[idx] = bt[ri[i * 64 + j] * NHEAD + h] + mask[nw * 4096 + i * 64 + j];
}

// ---------------------------------------------------------------------------
// GEMM1: qkv16[M,384] = fp16( x[M,256] @ W1[384,256]^T + b1 )
// CTA M=128, 256 thr, 6 N-chunks of 64, SINGLE W buffer, 2 CTAs/SM —
// the exposed W-chunk load is hidden by the co-resident CTA's compute.
// ---------------------------------------------------------------------------
#define PK1     264                    // padded pitch (halves) for K=256
#define OFF_W1  (128 * PK1 * 2)        // 67584
#define WBUF1   (64 * PK1 * 2)         // 33792
#define SMEM_G1 (OFF_W1 + WBUF1)       // 101376  -> 2 CTAs/SM

__global__ void __launch_bounds__(256, 2) psa_gemm1(
    const float* __restrict__ A,
    const __half* __restrict__ Whg,
    const float* __restrict__ bias,
    __half* __restrict__ out)
{
    extern __shared__ char smem[];
    const u32 sb = smem_u32(smem);
    const int t = threadIdx.x, lane = t & 31, wid = t >> 5;
    const int m0 = (wid & 3) * 32, n0 = (wid >> 2) * 32;
    const u32 wb = sb + OFF_W1;

    // prefetch W chunk 0 (32 uint4 per 64-row chunk row)
    {
        const uint4* gsrc = (const uint4*)Whg;
#pragma unroll
        for (int i = t; i < 2048; i += 256)
            CP_ASYNC16(wb + (i >> 5) * (PK1 * 2) + (i & 31) * 16, gsrc + i);
        CP_COMMIT();
    }

    // ---- convert A tile (128 x 256 fp32) -> fp16 ----
    {
        const float* Ag = A + (size_t)blockIdx.x * 128 * 256;
#pragma unroll 4
        for (int u = t; u < 128 * 32; u += 256) {
            int r = u >> 5, k0 = (u & 31) * 8;
            float4 a = *(const float4*)(Ag + r * 256 + k0);
            float4 b = *(const float4*)(Ag + r * 256 + k0 + 4);
            *(uint4*)(smem + r * (PK1 * 2) + k0 * 2) = make_uint4(
                pkh(a.x, a.y), pkh(a.z, a.w), pkh(b.x, b.y), pkh(b.z, b.w));
        }
    }

    u32 a_off[2], w_off[2];
#pragma unroll
    for (int mi = 0; mi < 2; mi++)
        a_off[mi] = (u32)((m0 + mi * 16 + (lane & 15)) * (PK1 * 2) + (lane >> 4) * 16);
    {
        int brow = ((lane >> 4) & 1) * 8 + (lane & 7);
        int bko  = ((lane >> 3) & 1) * 16;
#pragma unroll
        for (int nj = 0; nj < 2; nj++)
            w_off[nj] = (u32)((n0 + nj * 16 + brow) * (PK1 * 2) + bko);
    }

#pragma unroll 1
    for (int ch = 0; ch < 6; ch++) {
        CP_WAIT(0);          // chunk ch resident
        __syncthreads();     // + A conversion visible (ch==0) / buffer handoff

        float c[2][4][4];
#pragma unroll
        for (int ni = 0; ni < 4; ni++) {
            int col = ch * 64 + n0 + ni * 8 + (lane & 3) * 2;
            float b0 = __ldg(bias + col), b1 = __ldg(bias + col + 1);
#pragma unroll
            for (int mi = 0; mi < 2; mi++) {
                c[mi][ni][0] = b0; c[mi][ni][1] = b1;
                c[mi][ni][2] = b0; c[mi][ni][3] = b1;
            }
        }

#pragma unroll 4
        for (int k0 = 0; k0 < 256; k0 += 16) {
            u32 ah[2][4], wf[2][4];
#pragma unroll
            for (int mi = 0; mi < 2; mi++) ldsm4(ah[mi], sb + a_off[mi] + k0 * 2);
#pragma unroll
            for (int nj = 0; nj < 2; nj++) ldsm4(wf[nj], wb + w_off[nj] + k0 * 2);
#pragma unroll
            for (int mi = 0; mi < 2; mi++)
#pragma unroll
                for (int nt = 0; nt < 4; nt++)
                    mma_fp16(c[mi][nt], ah[mi], &wf[nt >> 1][(nt & 1) * 2]);
        }
        __syncthreads();     // all warps done reading W buffer

        if (ch + 1 < 6) {    // refill buffer; overlaps epilogue + other CTA
            const uint4* gsrc = (const uint4*)(Whg + (size_t)(ch + 1) * 64 * 256);
#pragma unroll
            for (int i = t; i < 2048; i += 256)
                CP_ASYNC16(wb + (i >> 5) * (PK1 * 2) + (i & 31) * 16, gsrc + i);
            CP_COMMIT();
        }

        // fp16 epilogue straight from frags
        {
            int rq = lane >> 2, cq = (lane & 3) * 2;
            __half* ob = out + (size_t)blockIdx.x * 128 * 384 + ch * 64;
#pragma unroll
            for (int mi = 0; mi < 2; mi++)
#pragma unroll
                for (int ni = 0; ni < 4; ni++) {
                    int rr = m0 + mi * 16 + rq, cc = n0 + ni * 8 + cq;
                    *(u32*)(ob + rr * 384 + cc)       = pkh(c[mi][ni][0], c[mi][ni][1]);
                    *(u32*)(ob + (rr + 8) * 384 + cc) = pkh(c[mi][ni][2], c[mi][ni][3]);
                }
        }
    }
}

// ---------------------------------------------------------------------------
// Fused HMMA attention + out-projection. One window per CTA, 256 threads,
// 2 CTAs/SM. One warp per head; K/V frags hoisted; W2 in a 128-row half-
// buffer reloaded between the two gemm2 N-halves.
// smem: qkv16 [64][392] (50176) | aoh [64][136] (17408) | W2buf [128][136] (34816)
// ---------------------------------------------------------------------------
#define PQ      392
#define B_AOH   50176
#define B_W2    67584
#define PA2     136
#define SMEM_B  102400

__global__ void __launch_bounds__(256, 2) psa_attn_proj(
    const __half* __restrict__ qkvg, const float* __restrict__ cmbg,
    const __half* __restrict__ W2h,  const float* __restrict__ pb,
    float* __restrict__ out)
{
    extern __shared__ char smem[];
    const u32 sb = smem_u32(smem);
    const int t = threadIdx.x, w = blockIdx.x;
    const int lane = t & 31, wid = t >> 5;

    // group 0: qkv tile (3072 uint4)
    {
        const uint4* qg = (const uint4*)qkvg + (size_t)w * 64 * 48;
#pragma unroll
        for (int i = 0; i < 12; i++) {
            int idx = t + 256 * i;
            int row = idx / 48, g = idx % 48;
            CP_ASYNC16(sb + row * (PQ * 2) + g * 16, qg + idx);
        }
        CP_COMMIT();
    }
    // group 1: W2 rows 0-127 into half-buffer (2048 uint4)
    {
        const uint4* gsrc = (const uint4*)W2h;
#pragma unroll
        for (int i = t; i < 2048; i += 256)
            CP_ASYNC16(sb + B_W2 + (i >> 4) * (PA2 * 2) + (i & 15) * 16, gsrc + i);
        CP_COMMIT();
    }
    CP_WAIT(1);        // qkv resident
    __syncthreads();

    // =====================================================================
    // Attention: one head per warp (h = wid), 4 passes of 16 rows
    // =====================================================================
    const int h  = wid;
    const int ql = lane >> 2, qc = (lane & 3) * 2;
    const float* cmb_h = cmbg + (((w & 63) * 8 + h) * 64) * 64;

    // K b-frags and V frags: pass-invariant, load once
    u32 kb[4][4], vb[4][4];
    {
        int brow = ((lane >> 4) & 1) * 8 + (lane & 7);
        int bko  = ((lane >> 3) & 1) * 16;
#pragma unroll
        for (int nt2 = 0; nt2 < 4; nt2++)
            ldsm4(kb[nt2], sb + (nt2 * 16 + brow) * (PQ * 2)
                           + (128 + h * 16) * 2 + bko);
        int vrow = ((lane >> 3) & 1) * 8 + (lane & 7);
        int vcol = (lane >> 4) * 8;
#pragma unroll
        for (int kt = 0; kt < 4; kt++)
            ldsm4t(vb[kt], sb + (kt * 16 + vrow) * (PQ * 2)
                           + (256 + h * 16 + vcol) * 2);
    }

#pragma unroll 1
    for (int mi = 0; mi < 4; mi++) {
        const int rb = mi * 16;

        u32 qa[4];
        ldsm4(qa, sb + (rb + (lane & 15)) * (PQ * 2) + h * 32 + (lane >> 4) * 16);

        // S = Q K^T  (scale pre-folded into q)
        float c[8][4];
#pragma unroll
        for (int nj = 0; nj < 8; nj++) { c[nj][0]=0.f; c[nj][1]=0.f; c[nj][2]=0.f; c[nj][3]=0.f; }
#pragma unroll
        for (int nj = 0; nj < 8; nj++)
            mma_fp16(c[nj], qa, &kb[nj >> 1][(nj & 1) * 2]);

        // logits = S + cmb; exp without max-shift (|logit| << 88)
        const int r0 = rb + ql;
        const float* cr0 = cmb_h + r0 * 64;
        const float* cr1 = cmb_h + (r0 + 8) * 64;
        float s0 = 0.f, s1 = 0.f;
#pragma unroll
        for (int nj = 0; nj < 8; nj++) {
            int col = nj * 8 + qc;
            float2 b0 = __ldg((const float2*)(cr0 + col));
            float2 b1 = __ldg((const float2*)(cr1 + col));
            c[nj][0] = __expf(c[nj][0] + b0.x);
            c[nj][1] = __expf(c[nj][1] + b0.y);
            c[nj][2] = __expf(c[nj][2] + b1.x);
            c[nj][3] = __expf(c[nj][3] + b1.y);
            s0 += c[nj][0] + c[nj][1];
            s1 += c[nj][2] + c[nj][3];
        }
        s0 += __shfl_xor_sync(0xffffffff, s0, 1);
        s0 += __shfl_xor_sync(0xffffffff, s0, 2);
        s1 += __shfl_xor_sync(0xffffffff, s1, 1);
        s1 += __shfl_xor_sync(0xffffffff, s1, 2);
        float inv0 = 1.0f / s0, inv1 = 1.0f / s1;

        // O = P V
        float o[2][4];
        o[0][0]=0.f;o[0][1]=0.f;o[0][2]=0.f;o[0][3]=0.f;
        o[1][0]=0.f;o[1][1]=0.f;o[1][2]=0.f;o[1][3]=0.f;
#pragma unroll
        for (int kt = 0; kt < 4; kt++) {
            u32 pa[4];
            pa[0] = pkh(c[2*kt][0]   * inv0, c[2*kt][1]   * inv0);
            pa[1] = pkh(c[2*kt][2]   * inv1, c[2*kt][3]   * inv1);
            pa[2] = pkh(c[2*kt+1][0] * inv0, c[2*kt+1][1] * inv0);
            pa[3] = pkh(c[2*kt+1][2] * inv1, c[2*kt+1][3] * inv1);
#pragma unroll
            for (int nt = 0; nt < 2; nt++)
                mma_fp16(o[nt], pa, &vb[kt][nt * 2]);
        }

        // store O -> aoh
#pragma unroll
        for (int nt = 0; nt < 2; nt++) {
            int d0 = h * 16 + nt * 8 + qc;
#pragma unroll
            for (int rh = 0; rh < 2; rh++) {
                u32 off = (u32)((r0 + rh * 8) * (PA2 * 2) + d0 * 2);
                *(u32*)(smem + B_AOH + off) = pkh(o[nt][rh * 2], o[nt][rh * 2 + 1]);
            }
        }
    }

    CP_WAIT(0);        // W2 half 0 resident
    __syncthreads();

    // =====================================================================
    // GEMM2: out[64,256] = ao[64,128] @ W2^T + pb, in two 128-col halves
    // =====================================================================
    const int m0g = (wid >> 1) * 16;
    const int n0g = (wid & 1) * 64;
    u32 a_off = (u32)(B_AOH + (m0g + (lane & 15)) * (PA2 * 2) + (lane >> 4) * 16);
    u32 w_off[4];
    {
        int brow = ((lane >> 4) & 1) * 8 + (lane & 7);
        int bko  = ((lane >> 3) & 1) * 16;
#pragma unroll
        for (int nj = 0; nj < 4; nj++)
            w_off[nj] = (u32)(B_W2 + (n0g + nj * 16 + brow) * (PA2 * 2) + bko);
    }
    int rq = lane >> 2, cq = (lane & 3) * 2;
    float* ob = out + (size_t)w * 64 * 256;

#pragma unroll 1
    for (int ph = 0; ph < 2; ph++) {
        float c[8][4];
#pragma unroll
        for (int nt = 0; nt < 8; nt++) {
            int col = ph * 128 + n0g + nt * 8 + cq;
            float b0 = __ldg(pb + col), b1 = __ldg(pb + col + 1);
            c[nt][0] = b0; c[nt][1] = b1; c[nt][2] = b0; c[nt][3] = b1;
        }

#pragma unroll 4
        for (int k0 = 0; k0 < 128; k0 += 16) {
            u32 ah[4], wf[4][4];
            ldsm4(ah, sb + a_off + k0 * 2);
#pragma unroll
            for (int nj = 0; nj < 4; nj++)
                ldsm4(wf[nj], sb + w_off[nj] + k0 * 2);
#pragma unroll
            for (int nt = 0; nt < 8; nt++)
                mma_fp16(c[nt], ah, &wf[nt >> 1][(nt & 1) * 2]);
        }

#pragma unroll
        for (int nt = 0; nt < 8; nt++) {
            int rr = m0g + rq, cc = ph * 128 + n0g + nt * 8 + cq;
            *(float2*)(ob + rr * 256 + cc)       = make_float2(c[nt][0], c[nt][1]);
            *(float2*)(ob + (rr + 8) * 256 + cc) = make_float2(c[nt][2], c[nt][3]);
        }

        if (ph == 0) {   // reload buffer with W2 rows 128-255
            __syncthreads();
            const uint4* gsrc = (const uint4*)W2h + 2048;
#pragma unroll
            for (int i = t; i < 2048; i += 256)
                CP_ASYNC16(sb + B_W2 + (i >> 4) * (PA2 * 2) + (i & 15) * 16, gsrc + i);
            CP_COMMIT();
            CP_WAIT(0);
            __syncthreads();
        }
    }
}

// ---------------------------------------------------------------------------
extern "C" void kernel_launch(void* const* d_in, const int* in_sizes, int n_in,
                              void* d_out, int out_size) {
    const float* x      = (const float*)d_in[0];
    const float* mask   = (const float*)d_in[1];
    const float* q_w    = (const float*)d_in[2];
    const float* q_b    = (const float*)d_in[3];
    const float* kv_w   = (const float*)d_in[4];
    const float* kv_b   = (const float*)d_in[5];
    const float* proj_w = (const float*)d_in[6];
    const float* proj_b = (const float*)d_in[7];
    const float* bt     = (const float*)d_in[8];
    const int*   ri     = (const int*)d_in[9];
    float* out = (float*)d_out;

    void *pqkv, *pw1h, *pw2h, *pb1, *pcmb;
    cudaGetSymbolAddress(&pqkv, g_qkvh);
    cudaGetSymbolAddress(&pw1h, g_w1h);
    cudaGetSymbolAddress(&pw2h, g_w2h);
    cudaGetSymbolAddress(&pb1,  g_b1);
    cudaGetSymbolAddress(&pcmb, g_cmb);

    cudaFuncSetAttribute(psa_gemm1,
                         cudaFuncAttributeMaxDynamicSharedMemorySize, SMEM_G1);
    cudaFuncSetAttribute(psa_attn_proj,
                         cudaFuncAttributeMaxDynamicSharedMemorySize, SMEM_B);

    psa_prep_w1<<<384, 256>>>(q_w, kv_w);
    psa_prep_w2<<<256, 128>>>(proj_w);
    psa_prep_b1<<<1, 384>>>(q_b, kv_b);
    psa_prep_cmb<<<4096, 512>>>(bt, ri, mask);

    // 1) qkv16 = fp16( x @ [q_w*scale;kv_w]^T + b )   (2 CTAs/SM)
    psa_gemm1<<<2048, 256, SMEM_G1>>>(
        x, (const __half*)pw1h, (const float*)pb1, (__half*)pqkv);

    // 2) fused HMMA attention + out-projection (2 CTAs/SM)
    psa_attn_proj<<<4096, 256, SMEM_B>>>(
        (const __half*)pqkv, (const float*)pcmb,
        (const __half*)pw2h, proj_b, out);
}

// round 15
// speedup vs baseline: 7.0688x; 1.0398x over previous
#include <cuda_runtime.h>
#include <cuda_fp16.h>
#include <cstdint>

typedef unsigned long long u64;
typedef unsigned int u32;

#define NTOK 64
#define NHEAD 8
#define PSA_SCALE 0.17677669529663687f
#define NWIN 4096

// ---------------------------------------------------------------------------
// Device scratch
// ---------------------------------------------------------------------------
__device__ __half g_qkvh[(size_t)NWIN * NTOK * 384];       // 201 MB qkv fp16
__device__ __half g_w1h[384 * 256];                        // fp16 weights (q rows pre-scaled)
__device__ __half g_w2h[256 * 128];
__device__ float  g_b1[384];                               // q part pre-scaled
__device__ float  g_cmb[64 * NHEAD * NTOK * NTOK];         // bias+mask, FRAGMENT-PERMUTED cols

// ---------------------------------------------------------------------------
// Helpers
// ---------------------------------------------------------------------------
__device__ __forceinline__ u32 smem_u32(const void* p) {
    u32 a;
    asm("{ .reg .u64 t; cvta.to.shared.u64 t, %1; cvt.u32.u64 %0, t; }"
        : "=r"(a) : "l"(p));
    return a;
}
__device__ __forceinline__ void ldsm4(u32* r, u32 addr) {
    asm volatile("ldmatrix.sync.aligned.m8n8.x4.shared.b16 {%0,%1,%2,%3}, [%4];"
                 : "=r"(r[0]), "=r"(r[1]), "=r"(r[2]), "=r"(r[3]) : "r"(addr));
}
__device__ __forceinline__ void ldsm4t(u32* r, u32 addr) {
    asm volatile("ldmatrix.sync.aligned.m8n8.x4.trans.shared.b16 {%0,%1,%2,%3}, [%4];"
                 : "=r"(r[0]), "=r"(r[1]), "=r"(r[2]), "=r"(r[3]) : "r"(addr));
}
__device__ __forceinline__ void mma_fp16(float* c, const u32* a, const u32* b) {
    asm volatile(
        "mma.sync.aligned.m16n8k16.row.col.f32.f16.f16.f32 "
        "{%0,%1,%2,%3}, {%4,%5,%6,%7}, {%8,%9}, {%0,%1,%2,%3};"
        : "+f"(c[0]), "+f"(c[1]), "+f"(c[2]), "+f"(c[3])
        : "r"(a[0]), "r"(a[1]), "r"(a[2]), "r"(a[3]), "r"(b[0]), "r"(b[1]));
}
#define CP_ASYNC16(dst, src) \
    asm volatile("cp.async.cg.shared.global [%0], [%1], 16;" :: "r"(dst), "l"(src))
#define CP_COMMIT() asm volatile("cp.async.commit_group;")
#define CP_WAIT(n)  asm volatile("cp.async.wait_group %0;" :: "n"(n))

__device__ __forceinline__ u32 h2u(__half2 v) { return *reinterpret_cast<u32*>(&v); }
__device__ __forceinline__ u32 pkh(float a, float b) {
    return h2u(__float22half2_rn(make_float2(a, b)));
}

// ---------------------------------------------------------------------------
// Merged prologue: blocks [0,4096) cmb | [4096,4288) w1 | [4288,4352) w2 | 4352 b1
// cmb column permutation: j = nj*8 + qg*2 + b  ->  p = qg*16 + nj*2 + b
// so each attn thread's 16 values per row-half are contiguous (4x float4).
// ---------------------------------------------------------------------------
__global__ void psa_prep_all(
    const float* __restrict__ bt,  const int* __restrict__ ri,
    const float* __restrict__ mask,
    const float* __restrict__ qw,  const float* __restrict__ kvw,
    const float* __restrict__ pw,
    const float* __restrict__ qb,  const float* __restrict__ kvb)
{
    int b = blockIdx.x, t = threadIdx.x;
    if (b < 4096) {                                  // cmb (permuted cols)
        int idx = b * 512 + t;
        int j = idx & 63, i = (idx >> 6) & 63, h = (idx >> 12) & 7, nw = idx >> 15;
        int p = ((j >> 1) & 3) * 16 + (j >> 3) * 2 + (j & 1);
        g_cmb[(idx - j) + p] =
            bt[ri[i * 64 + j] * NHEAD + h] + mask[nw * 4096 + i * 64 + j];
    } else if (b < 4288) {                           // w1: 2 rows per block
        int n = (b - 4096) * 2 + (t >> 8), k = t & 255;
        float v = (n < 128) ? qw[n * 256 + k] * PSA_SCALE
                            : kvw[(n - 128) * 256 + k];
        g_w1h[n * 256 + k] = __float2half_rn(v);
    } else if (b < 4352) {                           // w2: 4 rows per block
        int n = (b - 4288) * 4 + (t >> 7), k = t & 127;
        g_w2h[n * 128 + k] = __float2half_rn(pw[n * 128 + k]);
    } else {                                         // b1
        if (t < 384)
            g_b1[t] = (t < 128) ? qb[t] * PSA_SCALE : kvb[t - 128];
    }
}

// ---------------------------------------------------------------------------
// GEMM1: qkv16[M,384] = fp16( x[M,256] @ W1[384,256]^T + b1 )
// CTA M=128, 256 thr, 6 N-chunks of 64, single W buffer, 2 CTAs/SM.
// ---------------------------------------------------------------------------
#define PK1     264                    // padded pitch (halves) for K=256
#define OFF_W1  (128 * PK1 * 2)        // 67584
#define WBUF1   (64 * PK1 * 2)         // 33792
#define SMEM_G1 (OFF_W1 + WBUF1)       // 101376  -> 2 CTAs/SM

__global__ void __launch_bounds__(256, 2) psa_gemm1(
    const float* __restrict__ A,
    const __half* __restrict__ Whg,
    const float* __restrict__ bias,
    __half* __restrict__ out)
{
    extern __shared__ char smem[];
    const u32 sb = smem_u32(smem);
    const int t = threadIdx.x, lane = t & 31, wid = t >> 5;
    const int m0 = (wid & 3) * 32, n0 = (wid >> 2) * 32;
    const u32 wb = sb + OFF_W1;

    // prefetch W chunk 0 (32 uint4 per 64-row chunk row)
    {
        const uint4* gsrc = (const uint4*)Whg;
#pragma unroll
        for (int i = t; i < 2048; i += 256)
            CP_ASYNC16(wb + (i >> 5) * (PK1 * 2) + (i & 31) * 16, gsrc + i);
        CP_COMMIT();
    }

    // ---- convert A tile (128 x 256 fp32) -> fp16 ----
    {
        const float* Ag = A + (size_t)blockIdx.x * 128 * 256;
#pragma unroll 4
        for (int u = t; u < 128 * 32; u += 256) {
            int r = u >> 5, k0 = (u & 31) * 8;
            float4 a = *(const float4*)(Ag + r * 256 + k0);
            float4 b = *(const float4*)(Ag + r * 256 + k0 + 4);
            *(uint4*)(smem + r * (PK1 * 2) + k0 * 2) = make_uint4(
                pkh(a.x, a.y), pkh(a.z, a.w), pkh(b.x, b.y), pkh(b.z, b.w));
        }
    }

    u32 a_off[2], w_off[2];
#pragma unroll
    for (int mi = 0; mi < 2; mi++)
        a_off[mi] = (u32)((m0 + mi * 16 + (lane & 15)) * (PK1 * 2) + (lane >> 4) * 16);
    {
        int brow = ((lane >> 4) & 1) * 8 + (lane & 7);
        int bko  = ((lane >> 3) & 1) * 16;
#pragma unroll
        for (int nj = 0; nj < 2; nj++)
            w_off[nj] = (u32)((n0 + nj * 16 + brow) * (PK1 * 2) + bko);
    }

#pragma unroll 1
    for (int ch = 0; ch < 6; ch++) {
        CP_WAIT(0);
        __syncthreads();

        float c[2][4][4];
#pragma unroll
        for (int ni = 0; ni < 4; ni++) {
            int col = ch * 64 + n0 + ni * 8 + (lane & 3) * 2;
            float b0 = __ldg(bias + col), b1 = __ldg(bias + col + 1);
#pragma unroll
            for (int mi = 0; mi < 2; mi++) {
                c[mi][ni][0] = b0; c[mi][ni][1] = b1;
                c[mi][ni][2] = b0; c[mi][ni][3] = b1;
            }
        }

#pragma unroll 4
        for (int k0 = 0; k0 < 256; k0 += 16) {
            u32 ah[2][4], wf[2][4];
#pragma unroll
            for (int mi = 0; mi < 2; mi++) ldsm4(ah[mi], sb + a_off[mi] + k0 * 2);
#pragma unroll
            for (int nj = 0; nj < 2; nj++) ldsm4(wf[nj], wb + w_off[nj] + k0 * 2);
#pragma unroll
            for (int mi = 0; mi < 2; mi++)
#pragma unroll
                for (int nt = 0; nt < 4; nt++)
                    mma_fp16(c[mi][nt], ah[mi], &wf[nt >> 1][(nt & 1) * 2]);
        }
        __syncthreads();

        if (ch + 1 < 6) {    // refill buffer; overlaps epilogue + other CTA
            const uint4* gsrc = (const uint4*)(Whg + (size_t)(ch + 1) * 64 * 256);
#pragma unroll
            for (int i = t; i < 2048; i += 256)
                CP_ASYNC16(wb + (i >> 5) * (PK1 * 2) + (i & 31) * 16, gsrc + i);
            CP_COMMIT();
        }

        {
            int rq = lane >> 2, cq = (lane & 3) * 2;
            __half* ob = out + (size_t)blockIdx.x * 128 * 384 + ch * 64;
#pragma unroll
            for (int mi = 0; mi < 2; mi++)
#pragma unroll
                for (int ni = 0; ni < 4; ni++) {
                    int rr = m0 + mi * 16 + rq, cc = n0 + ni * 8 + cq;
                    *(u32*)(ob + rr * 384 + cc)       = pkh(c[mi][ni][0], c[mi][ni][1]);
                    *(u32*)(ob + (rr + 8) * 384 + cc) = pkh(c[mi][ni][2], c[mi][ni][3]);
                }
        }
    }
}

// ---------------------------------------------------------------------------
// Fused HMMA attention + out-projection. One window per CTA, 256 threads,
// 2 CTAs/SM. One warp per head; K/V frags hoisted; W2 half-buffer; cmb
// read as contiguous float4 (fragment-permuted table).
// smem: qkv16 [64][392] (50176) | aoh [64][136] (17408) | W2buf [128][136] (34816)
// ---------------------------------------------------------------------------
#define PQ      392
#define B_AOH   50176
#define B_W2    67584
#define PA2     136
#define SMEM_B  102400

__global__ void __launch_bounds__(256, 2) psa_attn_proj(
    const __half* __restrict__ qkvg, const float* __restrict__ cmbg,
    const __half* __restrict__ W2h,  const float* __restrict__ pb,
    float* __restrict__ out)
{
    extern __shared__ char smem[];
    const u32 sb = smem_u32(smem);
    const int t = threadIdx.x, w = blockIdx.x;
    const int lane = t & 31, wid = t >> 5;

    // group 0: qkv tile (3072 uint4)
    {
        const uint4* qg = (const uint4*)qkvg + (size_t)w * 64 * 48;
#pragma unroll
        for (int i = 0; i < 12; i++) {
            int idx = t + 256 * i;
            int row = idx / 48, g = idx % 48;
            CP_ASYNC16(sb + row * (PQ * 2) + g * 16, qg + idx);
        }
        CP_COMMIT();
    }
    // group 1: W2 rows 0-127 into half-buffer (2048 uint4)
    {
        const uint4* gsrc = (const uint4*)W2h;
#pragma unroll
        for (int i = t; i < 2048; i += 256)
            CP_ASYNC16(sb + B_W2 + (i >> 4) * (PA2 * 2) + (i & 15) * 16, gsrc + i);
        CP_COMMIT();
    }
    CP_WAIT(1);        // qkv resident
    __syncthreads();

    // =====================================================================
    // Attention: one head per warp (h = wid), 4 passes of 16 rows
    // =====================================================================
    const int h  = wid;
    const int ql = lane >> 2, qg4 = lane & 3;
    const float* cmb_h = cmbg + (((w & 63) * 8 + h) * 64) * 64;

    // K b-frags and V frags: pass-invariant, load once
    u32 kb[4][4], vb[4][4];
    {
        int brow = ((lane >> 4) & 1) * 8 + (lane & 7);
        int bko  = ((lane >> 3) & 1) * 16;
#pragma unroll
        for (int nt2 = 0; nt2 < 4; nt2++)
            ldsm4(kb[nt2], sb + (nt2 * 16 + brow) * (PQ * 2)
                           + (128 + h * 16) * 2 + bko);
        int vrow = ((lane >> 3) & 1) * 8 + (lane & 7);
        int vcol = (lane >> 4) * 8;
#pragma unroll
        for (int kt = 0; kt < 4; kt++)
            ldsm4t(vb[kt], sb + (kt * 16 + vrow) * (PQ * 2)
                           + (256 + h * 16 + vcol) * 2);
    }

#pragma unroll 1
    for (int mi = 0; mi < 4; mi++) {
        const int rb = mi * 16;

        u32 qa[4];
        ldsm4(qa, sb + (rb + (lane & 15)) * (PQ * 2) + h * 32 + (lane >> 4) * 16);

        // S = Q K^T  (scale pre-folded into q)
        float c[8][4];
#pragma unroll
        for (int nj = 0; nj < 8; nj++) { c[nj][0]=0.f; c[nj][1]=0.f; c[nj][2]=0.f; c[nj][3]=0.f; }
#pragma unroll
        for (int nj = 0; nj < 8; nj++)
            mma_fp16(c[nj], qa, &kb[nj >> 1][(nj & 1) * 2]);

        // logits = S + cmb (permuted table: 4x float4 per row-half)
        const int r0 = rb + ql;
        float bb0[16], bb1[16];
        {
            const float4* cr0 = (const float4*)(cmb_h + r0 * 64 + qg4 * 16);
            const float4* cr1 = (const float4*)(cmb_h + (r0 + 8) * 64 + qg4 * 16);
#pragma unroll
            for (int u = 0; u < 4; u++) {
                *(float4*)&bb0[4 * u] = __ldg(cr0 + u);
                *(float4*)&bb1[4 * u] = __ldg(cr1 + u);
            }
        }
        float s0 = 0.f, s1 = 0.f;
#pragma unroll
        for (int nj = 0; nj < 8; nj++) {
            c[nj][0] = __expf(c[nj][0] + bb0[nj * 2]);
            c[nj][1] = __expf(c[nj][1] + bb0[nj * 2 + 1]);
            c[nj][2] = __expf(c[nj][2] + bb1[nj * 2]);
            c[nj][3] = __expf(c[nj][3] + bb1[nj * 2 + 1]);
            s0 += c[nj][0] + c[nj][1];
            s1 += c[nj][2] + c[nj][3];
        }
        s0 += __shfl_xor_sync(0xffffffff, s0, 1);
        s0 += __shfl_xor_sync(0xffffffff, s0, 2);
        s1 += __shfl_xor_sync(0xffffffff, s1, 1);
        s1 += __shfl_xor_sync(0xffffffff, s1, 2);
        float inv0 = 1.0f / s0, inv1 = 1.0f / s1;

        // O = P V
        float o[2][4];
        o[0][0]=0.f;o[0][1]=0.f;o[0][2]=0.f;o[0][3]=0.f;
        o[1][0]=0.f;o[1][1]=0.f;o[1][2]=0.f;o[1][3]=0.f;
#pragma unroll
        for (int kt = 0; kt < 4; kt++) {
            u32 pa[4];
            pa[0] = pkh(c[2*kt][0]   * inv0, c[2*kt][1]   * inv0);
            pa[1] = pkh(c[2*kt][2]   * inv1, c[2*kt][3]   * inv1);
            pa[2] = pkh(c[2*kt+1][0] * inv0, c[2*kt+1][1] * inv0);
            pa[3] = pkh(c[2*kt+1][2] * inv1, c[2*kt+1][3] * inv1);
#pragma unroll
            for (int nt = 0; nt < 2; nt++)
                mma_fp16(o[nt], pa, &vb[kt][nt * 2]);
        }

        // store O -> aoh
#pragma unroll
        for (int nt = 0; nt < 2; nt++) {
            int d0 = h * 16 + nt * 8 + qg4 * 2;
#pragma unroll
            for (int rh = 0; rh < 2; rh++) {
                u32 off = (u32)((r0 + rh * 8) * (PA2 * 2) + d0 * 2);
                *(u32*)(smem + B_AOH + off) = pkh(o[nt][rh * 2], o[nt][rh * 2 + 1]);
            }
        }
    }

    CP_WAIT(0);        // W2 half 0 resident
    __syncthreads();

    // =====================================================================
    // GEMM2: out[64,256] = ao[64,128] @ W2^T + pb, two 128-col halves,
    // warp tile 32x32 (2M x 4N warp grid).
    // =====================================================================
    const int m0g = (wid & 1) * 32;
    const int n0g = (wid >> 1) * 32;
    u32 a_off[2];
#pragma unroll
    for (int mi = 0; mi < 2; mi++)
        a_off[mi] = (u32)(B_AOH + (m0g + mi * 16 + (lane & 15)) * (PA2 * 2)
                          + (lane >> 4) * 16);
    u32 w_off[2];
    {
        int brow = ((lane >> 4) & 1) * 8 + (lane & 7);
        int bko  = ((lane >> 3) & 1) * 16;
#pragma unroll
        for (int nj = 0; nj < 2; nj++)
            w_off[nj] = (u32)(B_W2 + (n0g + nj * 16 + brow) * (PA2 * 2) + bko);
    }
    int rq = lane >> 2, cq = (lane & 3) * 2;
    float* ob = out + (size_t)w * 64 * 256;

#pragma unroll 1
    for (int ph = 0; ph < 2; ph++) {
        float c[2][4][4];
#pragma unroll
        for (int nt = 0; nt < 4; nt++) {
            int col = ph * 128 + n0g + nt * 8 + cq;
            float b0 = __ldg(pb + col), b1 = __ldg(pb + col + 1);
#pragma unroll
            for (int mi = 0; mi < 2; mi++) {
                c[mi][nt][0] = b0; c[mi][nt][1] = b1;
                c[mi][nt][2] = b0; c[mi][nt][3] = b1;
            }
        }

#pragma unroll 4
        for (int k0 = 0; k0 < 128; k0 += 16) {
            u32 ah[2][4], wf[2][4];
#pragma unroll
            for (int mi = 0; mi < 2; mi++) ldsm4(ah[mi], sb + a_off[mi] + k0 * 2);
#pragma unroll
            for (int nj = 0; nj < 2; nj++) ldsm4(wf[nj], sb + w_off[nj] + k0 * 2);
#pragma unroll
            for (int mi = 0; mi < 2; mi++)
#pragma unroll
                for (int nt = 0; nt < 4; nt++)
                    mma_fp16(c[mi][nt], ah[mi], &wf[nt >> 1][(nt & 1) * 2]);
        }

#pragma unroll
        for (int mi = 0; mi < 2; mi++)
#pragma unroll
            for (int nt = 0; nt < 4; nt++) {
                int rr = m0g + mi * 16 + rq, cc = ph * 128 + n0g + nt * 8 + cq;
                *(float2*)(ob + rr * 256 + cc)       = make_float2(c[mi][nt][0], c[mi][nt][1]);
                *(float2*)(ob + (rr + 8) * 256 + cc) = make_float2(c[mi][nt][2], c[mi][nt][3]);
            }

        if (ph == 0) {   // reload buffer with W2 rows 128-255
            __syncthreads();
            const uint4* gsrc = (const uint4*)W2h + 2048;
#pragma unroll
            for (int i = t; i < 2048; i += 256)
                CP_ASYNC16(sb + B_W2 + (i >> 4) * (PA2 * 2) + (i & 15) * 16, gsrc + i);
            CP_COMMIT();
            CP_WAIT(0);
            __syncthreads();
        }
    }
}

// ---------------------------------------------------------------------------
extern "C" void kernel_launch(void* const* d_in, const int* in_sizes, int n_in,
                              void* d_out, int out_size) {
    const float* x      = (const float*)d_in[0];
    const float* mask   = (const float*)d_in[1];
    const float* q_w    = (const float*)d_in[2];
    const float* q_b    = (const float*)d_in[3];
    const float* kv_w   = (const float*)d_in[4];
    const float* kv_b   = (const float*)d_in[5];
    const float* proj_w = (const float*)d_in[6];
    const float* proj_b = (const float*)d_in[7];
    const float* bt     = (const float*)d_in[8];
    const int*   ri     = (const int*)d_in[9];
    float* out = (float*)d_out;

    void *pqkv, *pw1h, *pw2h, *pb1, *pcmb;
    cudaGetSymbolAddress(&pqkv, g_qkvh);
    cudaGetSymbolAddress(&pw1h, g_w1h);
    cudaGetSymbolAddress(&pw2h, g_w2h);
    cudaGetSymbolAddress(&pb1,  g_b1);
    cudaGetSymbolAddress(&pcmb, g_cmb);

    cudaFuncSetAttribute(psa_gemm1,
                         cudaFuncAttributeMaxDynamicSharedMemorySize, SMEM_G1);
    cudaFuncSetAttribute(psa_attn_proj,
                         cudaFuncAttributeMaxDynamicSharedMemorySize, SMEM_B);

    // 0) single merged prep launch
    psa_prep_all<<<4353, 512>>>(bt, ri, mask, q_w, kv_w, proj_w, q_b, kv_b);

    // 1) qkv16 = fp16( x @ [q_w*scale;kv_w]^T + b )   (2 CTAs/SM)
    psa_gemm1<<<2048, 256, SMEM_G1>>>(
        x, (const __half*)pw1h, (const float*)pb1, (__half*)pqkv);

    // 2) fused HMMA attention + out-projection (2 CTAs/SM)
    psa_attn_proj<<<4096, 256, SMEM_B>>>(
        (const __half*)pqkv, (const float*)pcmb,
        (const __half*)pw2h, proj_b, out);
}

// round 16
// speedup vs baseline: 7.1755x; 1.0151x over previous
#include <cuda_runtime.h>
#include <cuda_fp16.h>
#include <cstdint>

typedef unsigned long long u64;
typedef unsigned int u32;

#define NTOK 64
#define NHEAD 8
#define PSA_SCALE 0.17677669529663687f
#define NWIN 4096

// ---------------------------------------------------------------------------
// Device scratch
// ---------------------------------------------------------------------------
__device__ __half g_qkvh[(size_t)NWIN * NTOK * 384];       // 201 MB qkv fp16
__device__ __half g_w1h[384 * 256];                        // fp16 weights (q rows pre-scaled)
__device__ __half g_w2h[256 * 128];
__device__ float  g_b1[384];                               // q part pre-scaled
__device__ float  g_cmb[64 * NHEAD * NTOK * NTOK];         // bias+mask, FRAGMENT-PERMUTED cols

// ---------------------------------------------------------------------------
// Helpers
// ---------------------------------------------------------------------------
__device__ __forceinline__ u32 smem_u32(const void* p) {
    u32 a;
    asm("{ .reg .u64 t; cvta.to.shared.u64 t, %1; cvt.u32.u64 %0, t; }"
        : "=r"(a) : "l"(p));
    return a;
}
__device__ __forceinline__ void ldsm4(u32* r, u32 addr) {
    asm volatile("ldmatrix.sync.aligned.m8n8.x4.shared.b16 {%0,%1,%2,%3}, [%4];"
                 : "=r"(r[0]), "=r"(r[1]), "=r"(r[2]), "=r"(r[3]) : "r"(addr));
}
__device__ __forceinline__ void ldsm4t(u32* r, u32 addr) {
    asm volatile("ldmatrix.sync.aligned.m8n8.x4.trans.shared.b16 {%0,%1,%2,%3}, [%4];"
                 : "=r"(r[0]), "=r"(r[1]), "=r"(r[2]), "=r"(r[3]) : "r"(addr));
}
__device__ __forceinline__ void mma_fp16(float* c, const u32* a, const u32* b) {
    asm volatile(
        "mma.sync.aligned.m16n8k16.row.col.f32.f16.f16.f32 "
        "{%0,%1,%2,%3}, {%4,%5,%6,%7}, {%8,%9}, {%0,%1,%2,%3};"
        : "+f"(c[0]), "+f"(c[1]), "+f"(c[2]), "+f"(c[3])
        : "r"(a[0]), "r"(a[1]), "r"(a[2]), "r"(a[3]), "r"(b[0]), "r"(b[1]));
}
#define CP_ASYNC16(dst, src) \
    asm volatile("cp.async.cg.shared.global [%0], [%1], 16;" :: "r"(dst), "l"(src))
#define CP_COMMIT() asm volatile("cp.async.commit_group;")
#define CP_WAIT(n)  asm volatile("cp.async.wait_group %0;" :: "n"(n))

__device__ __forceinline__ u32 h2u(__half2 v) { return *reinterpret_cast<u32*>(&v); }
__device__ __forceinline__ u32 pkh(float a, float b) {
    return h2u(__float22half2_rn(make_float2(a, b)));
}

// ---------------------------------------------------------------------------
// Merged prologue: blocks [0,4096) cmb | [4096,4288) w1 | [4288,4352) w2 | 4352 b1
// cmb column permutation: j = nj*8 + qg*2 + b  ->  p = qg*16 + nj*2 + b
// ---------------------------------------------------------------------------
__global__ void psa_prep_all(
    const float* __restrict__ bt,  const int* __restrict__ ri,
    const float* __restrict__ mask,
    const float* __restrict__ qw,  const float* __restrict__ kvw,
    const float* __restrict__ pw,
    const float* __restrict__ qb,  const float* __restrict__ kvb)
{
    int b = blockIdx.x, t = threadIdx.x;
    if (b < 4096) {                                  // cmb (permuted cols)
        int idx = b * 512 + t;
        int j = idx & 63, i = (idx >> 6) & 63, h = (idx >> 12) & 7, nw = idx >> 15;
        int p = ((j >> 1) & 3) * 16 + (j >> 3) * 2 + (j & 1);
        g_cmb[(idx - j) + p] =
            bt[ri[i * 64 + j] * NHEAD + h] + mask[nw * 4096 + i * 64 + j];
    } else if (b < 4288) {                           // w1: 2 rows per block
        int n = (b - 4096) * 2 + (t >> 8), k = t & 255;
        float v = (n < 128) ? qw[n * 256 + k] * PSA_SCALE
                            : kvw[(n - 128) * 256 + k];
        g_w1h[n * 256 + k] = __float2half_rn(v);
    } else if (b < 4352) {                           // w2: 4 rows per block
        int n = (b - 4288) * 4 + (t >> 7), k = t & 127;
        g_w2h[n * 128 + k] = __float2half_rn(pw[n * 128 + k]);
    } else {                                         // b1
        if (t < 384)
            g_b1[t] = (t < 128) ? qb[t] * PSA_SCALE : kvb[t - 128];
    }
}

// ---------------------------------------------------------------------------
// GEMM1: qkv16[M,384] = fp16( x[M,256] @ W1[384,256]^T + b1 )
// CTA M=128, 256 thr, 6 N-chunks of 64, single W buffer, 2 CTAs/SM.
// ---------------------------------------------------------------------------
#define PK1     264                    // padded pitch (halves) for K=256
#define OFF_W1  (128 * PK1 * 2)        // 67584
#define WBUF1   (64 * PK1 * 2)         // 33792
#define SMEM_G1 (OFF_W1 + WBUF1)       // 101376  -> 2 CTAs/SM

__global__ void __launch_bounds__(256, 2) psa_gemm1(
    const float* __restrict__ A,
    const __half* __restrict__ Whg,
    const float* __restrict__ bias,
    __half* __restrict__ out)
{
    extern __shared__ char smem[];
    const u32 sb = smem_u32(smem);
    const int t = threadIdx.x, lane = t & 31, wid = t >> 5;
    const int m0 = (wid & 3) * 32, n0 = (wid >> 2) * 32;
    const u32 wb = sb + OFF_W1;

    // prefetch W chunk 0 (32 uint4 per 64-row chunk row)
    {
        const uint4* gsrc = (const uint4*)Whg;
#pragma unroll
        for (int i = t; i < 2048; i += 256)
            CP_ASYNC16(wb + (i >> 5) * (PK1 * 2) + (i & 31) * 16, gsrc + i);
        CP_COMMIT();
    }

    // ---- convert A tile (128 x 256 fp32) -> fp16 ----
    {
        const float* Ag = A + (size_t)blockIdx.x * 128 * 256;
#pragma unroll 4
        for (int u = t; u < 128 * 32; u += 256) {
            int r = u >> 5, k0 = (u & 31) * 8;
            float4 a = *(const float4*)(Ag + r * 256 + k0);
            float4 b = *(const float4*)(Ag + r * 256 + k0 + 4);
            *(uint4*)(smem + r * (PK1 * 2) + k0 * 2) = make_uint4(
                pkh(a.x, a.y), pkh(a.z, a.w), pkh(b.x, b.y), pkh(b.z, b.w));
        }
    }

    u32 a_off[2], w_off[2];
#pragma unroll
    for (int mi = 0; mi < 2; mi++)
        a_off[mi] = (u32)((m0 + mi * 16 + (lane & 15)) * (PK1 * 2) + (lane >> 4) * 16);
    {
        int brow = ((lane >> 4) & 1) * 8 + (lane & 7);
        int bko  = ((lane >> 3) & 1) * 16;
#pragma unroll
        for (int nj = 0; nj < 2; nj++)
            w_off[nj] = (u32)((n0 + nj * 16 + brow) * (PK1 * 2) + bko);
    }

#pragma unroll 1
    for (int ch = 0; ch < 6; ch++) {
        CP_WAIT(0);
        __syncthreads();

        float c[2][4][4];
#pragma unroll
        for (int ni = 0; ni < 4; ni++) {
            int col = ch * 64 + n0 + ni * 8 + (lane & 3) * 2;
            float b0 = __ldg(bias + col), b1 = __ldg(bias + col + 1);
#pragma unroll
            for (int mi = 0; mi < 2; mi++) {
                c[mi][ni][0] = b0; c[mi][ni][1] = b1;
                c[mi][ni][2] = b0; c[mi][ni][3] = b1;
            }
        }

#pragma unroll 4
        for (int k0 = 0; k0 < 256; k0 += 16) {
            u32 ah[2][4], wf[2][4];
#pragma unroll
            for (int mi = 0; mi < 2; mi++) ldsm4(ah[mi], sb + a_off[mi] + k0 * 2);
#pragma unroll
            for (int nj = 0; nj < 2; nj++) ldsm4(wf[nj], wb + w_off[nj] + k0 * 2);
#pragma unroll
            for (int mi = 0; mi < 2; mi++)
#pragma unroll
                for (int nt = 0; nt < 4; nt++)
                    mma_fp16(c[mi][nt], ah[mi], &wf[nt >> 1][(nt & 1) * 2]);
        }
        __syncthreads();

        if (ch + 1 < 6) {    // refill buffer; overlaps epilogue + other CTA
            const uint4* gsrc = (const uint4*)(Whg + (size_t)(ch + 1) * 64 * 256);
#pragma unroll
            for (int i = t; i < 2048; i += 256)
                CP_ASYNC16(wb + (i >> 5) * (PK1 * 2) + (i & 31) * 16, gsrc + i);
            CP_COMMIT();
        }

        {
            int rq = lane >> 2, cq = (lane & 3) * 2;
            __half* ob = out + (size_t)blockIdx.x * 128 * 384 + ch * 64;
#pragma unroll
            for (int mi = 0; mi < 2; mi++)
#pragma unroll
                for (int ni = 0; ni < 4; ni++) {
                    int rr = m0 + mi * 16 + rq, cc = n0 + ni * 8 + cq;
                    *(u32*)(ob + rr * 384 + cc)       = pkh(c[mi][ni][0], c[mi][ni][1]);
                    *(u32*)(ob + (rr + 8) * 384 + cc) = pkh(c[mi][ni][2], c[mi][ni][3]);
                }
        }
    }
}

// ---------------------------------------------------------------------------
// Fused HMMA attention + out-projection. One window per CTA, 256 threads,
// 2 CTAs/SM. W2 half0 in its own buffer; half1 streamed into the DEAD qkv
// region during gemm2 phase 0 (no exposed reload).
// smem: qkv16 [64][392] (50176, becomes W2-half1 buffer) |
//       aoh [64][136] (17408) | W2buf [128][136] (34816)
// ---------------------------------------------------------------------------
#define PQ      392
#define B_AOH   50176
#define B_W2    67584
#define PA2     136
#define SMEM_B  102400

__global__ void __launch_bounds__(256, 2) psa_attn_proj(
    const __half* __restrict__ qkvg, const float* __restrict__ cmbg,
    const __half* __restrict__ W2h,  const float* __restrict__ pb,
    float* __restrict__ out)
{
    extern __shared__ char smem[];
    const u32 sb = smem_u32(smem);
    const int t = threadIdx.x, w = blockIdx.x;
    const int lane = t & 31, wid = t >> 5;

    // group 0: qkv tile (3072 uint4)
    {
        const uint4* qg = (const uint4*)qkvg + (size_t)w * 64 * 48;
#pragma unroll
        for (int i = 0; i < 12; i++) {
            int idx = t + 256 * i;
            int row = idx / 48, g = idx % 48;
            CP_ASYNC16(sb + row * (PQ * 2) + g * 16, qg + idx);
        }
        CP_COMMIT();
    }
    // group 1: W2 rows 0-127 into the dedicated half-buffer (2048 uint4)
    {
        const uint4* gsrc = (const uint4*)W2h;
#pragma unroll
        for (int i = t; i < 2048; i += 256)
            CP_ASYNC16(sb + B_W2 + (i >> 4) * (PA2 * 2) + (i & 15) * 16, gsrc + i);
        CP_COMMIT();
    }
    CP_WAIT(1);        // qkv resident
    __syncthreads();

    // =====================================================================
    // Attention: one head per warp (h = wid), 4 passes of 16 rows
    // =====================================================================
    const int h  = wid;
    const int ql = lane >> 2, qg4 = lane & 3;
    const float* cmb_h = cmbg + (((w & 63) * 8 + h) * 64) * 64;

    // K b-frags and V frags: pass-invariant, load once
    u32 kb[4][4], vb[4][4];
    {
        int brow = ((lane >> 4) & 1) * 8 + (lane & 7);
        int bko  = ((lane >> 3) & 1) * 16;
#pragma unroll
        for (int nt2 = 0; nt2 < 4; nt2++)
            ldsm4(kb[nt2], sb + (nt2 * 16 + brow) * (PQ * 2)
                           + (128 + h * 16) * 2 + bko);
        int vrow = ((lane >> 3) & 1) * 8 + (lane & 7);
        int vcol = (lane >> 4) * 8;
#pragma unroll
        for (int kt = 0; kt < 4; kt++)
            ldsm4t(vb[kt], sb + (kt * 16 + vrow) * (PQ * 2)
                           + (256 + h * 16 + vcol) * 2);
    }

#pragma unroll 1
    for (int mi = 0; mi < 4; mi++) {
        const int rb = mi * 16;

        u32 qa[4];
        ldsm4(qa, sb + (rb + (lane & 15)) * (PQ * 2) + h * 32 + (lane >> 4) * 16);

        // S = Q K^T  (scale pre-folded into q)
        float c[8][4];
#pragma unroll
        for (int nj = 0; nj < 8; nj++) { c[nj][0]=0.f; c[nj][1]=0.f; c[nj][2]=0.f; c[nj][3]=0.f; }
#pragma unroll
        for (int nj = 0; nj < 8; nj++)
            mma_fp16(c[nj], qa, &kb[nj >> 1][(nj & 1) * 2]);

        // logits = S + cmb (permuted table: 4x float4 per row-half)
        const int r0 = rb + ql;
        float bb0[16], bb1[16];
        {
            const float4* cr0 = (const float4*)(cmb_h + r0 * 64 + qg4 * 16);
            const float4* cr1 = (const float4*)(cmb_h + (r0 + 8) * 64 + qg4 * 16);
#pragma unroll
            for (int u = 0; u < 4; u++) {
                *(float4*)&bb0[4 * u] = __ldg(cr0 + u);
                *(float4*)&bb1[4 * u] = __ldg(cr1 + u);
            }
        }
        float s0 = 0.f, s1 = 0.f;
#pragma unroll
        for (int nj = 0; nj < 8; nj++) {
            c[nj][0] = __expf(c[nj][0] + bb0[nj * 2]);
            c[nj][1] = __expf(c[nj][1] + bb0[nj * 2 + 1]);
            c[nj][2] = __expf(c[nj][2] + bb1[nj * 2]);
            c[nj][3] = __expf(c[nj][3] + bb1[nj * 2 + 1]);
            s0 += c[nj][0] + c[nj][1];
            s1 += c[nj][2] + c[nj][3];
        }
        s0 += __shfl_xor_sync(0xffffffff, s0, 1);
        s0 += __shfl_xor_sync(0xffffffff, s0, 2);
        s1 += __shfl_xor_sync(0xffffffff, s1, 1);
        s1 += __shfl_xor_sync(0xffffffff, s1, 2);
        float inv0 = 1.0f / s0, inv1 = 1.0f / s1;

        // O = P V
        float o[2][4];
        o[0][0]=0.f;o[0][1]=0.f;o[0][2]=0.f;o[0][3]=0.f;
        o[1][0]=0.f;o[1][1]=0.f;o[1][2]=0.f;o[1][3]=0.f;
#pragma unroll
        for (int kt = 0; kt < 4; kt++) {
            u32 pa[4];
            pa[0] = pkh(c[2*kt][0]   * inv0, c[2*kt][1]   * inv0);
            pa[1] = pkh(c[2*kt][2]   * inv1, c[2*kt][3]   * inv1);
            pa[2] = pkh(c[2*kt+1][0] * inv0, c[2*kt+1][1] * inv0);
            pa[3] = pkh(c[2*kt+1][2] * inv1, c[2*kt+1][3] * inv1);
#pragma unroll
            for (int nt = 0; nt < 2; nt++)
                mma_fp16(o[nt], pa, &vb[kt][nt * 2]);
        }

        // store O -> aoh
#pragma unroll
        for (int nt = 0; nt < 2; nt++) {
            int d0 = h * 16 + nt * 8 + qg4 * 2;
#pragma unroll
            for (int rh = 0; rh < 2; rh++) {
                u32 off = (u32)((r0 + rh * 8) * (PA2 * 2) + d0 * 2);
                *(u32*)(smem + B_AOH + off) = pkh(o[nt][rh * 2], o[nt][rh * 2 + 1]);
            }
        }
    }

    __syncthreads();   // all attention reads of qkv done; region is dead

    // group 2: W2 rows 128-255 streamed into the dead qkv region
    {
        const uint4* gsrc = (const uint4*)W2h + 2048;
#pragma unroll
        for (int i = t; i < 2048; i += 256)
            CP_ASYNC16(sb + (i >> 4) * (PA2 * 2) + (i & 15) * 16, gsrc + i);
        CP_COMMIT();
    }
    CP_WAIT(1);        // W2 half 0 resident (group 1); half 1 in flight
    __syncthreads();

    // =====================================================================
    // GEMM2: out[64,256] = ao[64,128] @ W2^T + pb, two 128-col halves,
    // warp tile 32x32. ph0 from B_W2; ph1 from the qkv-region buffer
    // (loads overlap ph0 compute).
    // =====================================================================
    const int m0g = (wid & 1) * 32;
    const int n0g = (wid >> 1) * 32;
    u32 a_off[2];
#pragma unroll
    for (int mi = 0; mi < 2; mi++)
        a_off[mi] = (u32)(B_AOH + (m0g + mi * 16 + (lane & 15)) * (PA2 * 2)
                          + (lane >> 4) * 16);
    u32 w_off[2];
    {
        int brow = ((lane >> 4) & 1) * 8 + (lane & 7);
        int bko  = ((lane >> 3) & 1) * 16;
#pragma unroll
        for (int nj = 0; nj < 2; nj++)
            w_off[nj] = (u32)((n0g + nj * 16 + brow) * (PA2 * 2) + bko);
    }
    int rq = lane >> 2, cq = (lane & 3) * 2;
    float* ob = out + (size_t)w * 64 * 256;

#pragma unroll 1
    for (int ph = 0; ph < 2; ph++) {
        const u32 wbase = sb + (ph == 0 ? B_W2 : 0);

        float c[2][4][4];
#pragma unroll
        for (int nt = 0; nt < 4; nt++) {
            int col = ph * 128 + n0g + nt * 8 + cq;
            float b0 = __ldg(pb + col), b1 = __ldg(pb + col + 1);
#pragma unroll
            for (int mi = 0; mi < 2; mi++) {
                c[mi][nt][0] = b0; c[mi][nt][1] = b1;
                c[mi][nt][2] = b0; c[mi][nt][3] = b1;
            }
        }

#pragma unroll 4
        for (int k0 = 0; k0 < 128; k0 += 16) {
            u32 ah[2][4], wf[2][4];
#pragma unroll
            for (int mi = 0; mi < 2; mi++) ldsm4(ah[mi], sb + a_off[mi] + k0 * 2);
#pragma unroll
            for (int nj = 0; nj < 2; nj++) ldsm4(wf[nj], wbase + w_off[nj] + k0 * 2);
#pragma unroll
            for (int mi = 0; mi < 2; mi++)
#pragma unroll
                for (int nt = 0; nt < 4; nt++)
                    mma_fp16(c[mi][nt], ah[mi], &wf[nt >> 1][(nt & 1) * 2]);
        }

#pragma unroll
        for (int mi = 0; mi < 2; mi++)
#pragma unroll
            for (int nt = 0; nt < 4; nt++) {
                int rr = m0g + mi * 16 + rq, cc = ph * 128 + n0g + nt * 8 + cq;
                *(float2*)(ob + rr * 256 + cc)       = make_float2(c[mi][nt][0], c[mi][nt][1]);
                *(float2*)(ob + (rr + 8) * 256 + cc) = make_float2(c[mi][nt][2], c[mi][nt][3]);
            }

        if (ph == 0) {
            CP_WAIT(0);        // half 1 resident (already overlapped with ph0)
            __syncthreads();
        }
    }
}

// ---------------------------------------------------------------------------
extern "C" void kernel_launch(void* const* d_in, const int* in_sizes, int n_in,
                              void* d_out, int out_size) {
    const float* x      = (const float*)d_in[0];
    const float* mask   = (const float*)d_in[1];
    const float* q_w    = (const float*)d_in[2];
    const float* q_b    = (const float*)d_in[3];
    const float* kv_w   = (const float*)d_in[4];
    const float* kv_b   = (const float*)d_in[5];
    const float* proj_w = (const float*)d_in[6];
    const float* proj_b = (const float*)d_in[7];
    const float* bt     = (const float*)d_in[8];
    const int*   ri     = (const int*)d_in[9];
    float* out = (float*)d_out;

    void *pqkv, *pw1h, *pw2h, *pb1, *pcmb;
    cudaGetSymbolAddress(&pqkv, g_qkvh);
    cudaGetSymbolAddress(&pw1h, g_w1h);
    cudaGetSymbolAddress(&pw2h, g_w2h);
    cudaGetSymbolAddress(&pb1,  g_b1);
    cudaGetSymbolAddress(&pcmb, g_cmb);

    cudaFuncSetAttribute(psa_gemm1,
                         cudaFuncAttributeMaxDynamicSharedMemorySize, SMEM_G1);
    cudaFuncSetAttribute(psa_attn_proj,
                         cudaFuncAttributeMaxDynamicSharedMemorySize, SMEM_B);

    // 0) single merged prep launch
    psa_prep_all<<<4353, 512>>>(bt, ri, mask, q_w, kv_w, proj_w, q_b, kv_b);

    // 1) qkv16 = fp16( x @ [q_w*scale;kv_w]^T + b )   (2 CTAs/SM)
    psa_gemm1<<<2048, 256, SMEM_G1>>>(
        x, (const __half*)pw1h, (const float*)pb1, (__half*)pqkv);

    // 2) fused HMMA attention + out-projection (2 CTAs/SM)
    psa_attn_proj<<<4096, 256, SMEM_B>>>(
        (const __half*)pqkv, (const float*)pcmb,
        (const __half*)pw2h, proj_b, out);
}